// round 4
// baseline (speedup 1.0000x reference)
#include <cuda_runtime.h>

#define BB 4
#define SS 4096
#define DD 1024
#define HH 64

// Scratch for Q (pre-scaled by 1/sqrt(64)), K, V. 4 MB each — static device
// arrays, no runtime allocation.
__device__ float g_Q[BB * SS * HH];
__device__ float g_K[BB * SS * HH];
__device__ float g_V[BB * SS * HH];

// ---------------------------------------------------------------------------
// Kernel A: fused QKV projection.  C[M=16384, 64] = x[M, 1024] * W[1024, 64]
// blockIdx.x: M-tile (64 rows); blockIdx.y: 0=Q, 1=K, 2=V.
// BM=64, BN=64, BK=16; 256 threads as 16x16, 4x4 outputs per thread.
// ---------------------------------------------------------------------------
__global__ __launch_bounds__(256) void qkv_kernel(
    const float* __restrict__ x,
    const float* __restrict__ Wq,
    const float* __restrict__ Wk,
    const float* __restrict__ Wv)
{
    __shared__ float As[16 * 68];   // [k][row], padded stride 68
    __shared__ float Bs[16 * 64];   // [k][col]

    const int m0 = blockIdx.x * 64;
    const float* W;
    float* out;
    float scale;
    if (blockIdx.y == 0)      { W = Wq; out = g_Q; scale = 0.125f; }  // 1/sqrt(64)
    else if (blockIdx.y == 1) { W = Wk; out = g_K; scale = 1.0f; }
    else                      { W = Wv; out = g_V; scale = 1.0f; }

    const int tid = threadIdx.x;
    const int ty = tid >> 4;          // 0..15
    const int tx = tid & 15;          // 0..15
    const int lrow = tid >> 2;        // 0..63  (A-tile loader row)
    const int lk0  = (tid & 3) * 4;   // 0,4,8,12
    const int wkr  = tid >> 4;        // 0..15  (B-tile loader k-row)
    const int wc0  = (tid & 15) * 4;  // 0..60

    float acc[4][4];
    #pragma unroll
    for (int i = 0; i < 4; ++i)
        #pragma unroll
        for (int j = 0; j < 4; ++j) acc[i][j] = 0.0f;

    for (int kt = 0; kt < DD; kt += 16) {
        const float4 a4 = *(const float4*)&x[(size_t)(m0 + lrow) * DD + kt + lk0];
        const float4 b4 = *(const float4*)&W[(size_t)(kt + wkr) * HH + wc0];
        As[(lk0 + 0) * 68 + lrow] = a4.x;
        As[(lk0 + 1) * 68 + lrow] = a4.y;
        As[(lk0 + 2) * 68 + lrow] = a4.z;
        As[(lk0 + 3) * 68 + lrow] = a4.w;
        *(float4*)&Bs[wkr * 64 + wc0] = b4;
        __syncthreads();

        #pragma unroll
        for (int k = 0; k < 16; ++k) {
            const float4 av = *(const float4*)&As[k * 68 + 4 * ty];
            const float4 bv = *(const float4*)&Bs[k * 64 + 4 * tx];
            const float a[4] = {av.x, av.y, av.z, av.w};
            const float b[4] = {bv.x, bv.y, bv.z, bv.w};
            #pragma unroll
            for (int i = 0; i < 4; ++i)
                #pragma unroll
                for (int j = 0; j < 4; ++j)
                    acc[i][j] = fmaf(a[i], b[j], acc[i][j]);
        }
        __syncthreads();
    }

    #pragma unroll
    for (int i = 0; i < 4; ++i) {
        float4 r;
        r.x = acc[i][0] * scale;
        r.y = acc[i][1] * scale;
        r.z = acc[i][2] * scale;
        r.w = acc[i][3] * scale;
        *(float4*)&out[(size_t)(m0 + 4 * ty + i) * HH + 4 * tx] = r;
    }
}

// ---------------------------------------------------------------------------
// Kernel B: causal flash attention, fp32.
// grid (32, 4): blockIdx.x = pair id p -> handles q-blocks {p, 63-p}
// (work = (p+1) + (64-p) = 65 tiles, perfectly balanced; 128 CTAs ~ 1/SM).
// 256 threads (16x16), 64x64 tiles, online softmax, P via padded smem.
// ---------------------------------------------------------------------------
__global__ __launch_bounds__(256, 1) void attn_kernel(float* __restrict__ out)
{
    extern __shared__ float sm[];
    float* Qt = sm;                 // [k][r]  64 x stride 68
    float* Kt = sm + 64 * 68;       // [k][c]
    float* Vs = sm + 2 * 64 * 68;   // [c][h]
    float* Pt = sm + 3 * 64 * 68;   // [c][r]

    const int b   = blockIdx.y;
    const int pid = blockIdx.x;     // 0..31
    const int tid = threadIdx.x;
    const int ty = tid >> 4, tx = tid & 15;
    const int lr  = tid >> 2;        // 0..63 loader row
    const int lk0 = (tid & 3) * 16;  // 0,16,32,48

    const float* Q = g_Q + (size_t)b * SS * HH;
    const float* K = g_K + (size_t)b * SS * HH;
    const float* V = g_V + (size_t)b * SS * HH;

    for (int pass = 0; pass < 2; ++pass) {
        const int qb = pass ? (63 - pid) : pid;

        // Load Q tile transposed into Qt[k][r]
        {
            const float* gq = Q + (size_t)(qb * 64 + lr) * HH + lk0;
            #pragma unroll
            for (int u = 0; u < 4; ++u) {
                const float4 q4 = *(const float4*)(gq + 4 * u);
                Qt[(lk0 + 4 * u + 0) * 68 + lr] = q4.x;
                Qt[(lk0 + 4 * u + 1) * 68 + lr] = q4.y;
                Qt[(lk0 + 4 * u + 2) * 68 + lr] = q4.z;
                Qt[(lk0 + 4 * u + 3) * 68 + lr] = q4.w;
            }
        }
        __syncthreads();

        float m_i[4], l_i[4], o[4][4];
        #pragma unroll
        for (int i = 0; i < 4; ++i) {
            m_i[i] = -1e30f;
            l_i[i] = 0.0f;
            #pragma unroll
            for (int j = 0; j < 4; ++j) o[i][j] = 0.0f;
        }

        for (int kb = 0; kb <= qb; ++kb) {
            // Load K tile (transposed) and V tile
            {
                const float* gk = K + (size_t)(kb * 64 + lr) * HH + lk0;
                const float* gv = V + (size_t)(kb * 64 + lr) * HH + lk0;
                #pragma unroll
                for (int u = 0; u < 4; ++u) {
                    const float4 k4 = *(const float4*)(gk + 4 * u);
                    Kt[(lk0 + 4 * u + 0) * 68 + lr] = k4.x;
                    Kt[(lk0 + 4 * u + 1) * 68 + lr] = k4.y;
                    Kt[(lk0 + 4 * u + 2) * 68 + lr] = k4.z;
                    Kt[(lk0 + 4 * u + 3) * 68 + lr] = k4.w;
                    const float4 v4 = *(const float4*)(gv + 4 * u);
                    *(float4*)&Vs[lr * 68 + lk0 + 4 * u] = v4;
                }
            }
            __syncthreads();

            // S = Q K^T  (Q already carries 1/sqrt(H))
            float s[4][4];
            #pragma unroll
            for (int i = 0; i < 4; ++i)
                #pragma unroll
                for (int j = 0; j < 4; ++j) s[i][j] = 0.0f;

            #pragma unroll 16
            for (int k = 0; k < 64; ++k) {
                const float4 qa = *(const float4*)&Qt[k * 68 + 4 * ty];
                const float4 ka = *(const float4*)&Kt[k * 68 + 4 * tx];
                const float qv[4] = {qa.x, qa.y, qa.z, qa.w};
                const float kv[4] = {ka.x, ka.y, ka.z, ka.w};
                #pragma unroll
                for (int i = 0; i < 4; ++i)
                    #pragma unroll
                    for (int j = 0; j < 4; ++j)
                        s[i][j] = fmaf(qv[i], kv[j], s[i][j]);
            }

            // Causal mask: only the diagonal tile needs it
            if (kb == qb) {
                #pragma unroll
                for (int i = 0; i < 4; ++i)
                    #pragma unroll
                    for (int j = 0; j < 4; ++j)
                        if (4 * tx + j > 4 * ty + i) s[i][j] = -1e30f;
            }

            // Online softmax (row reductions across the 16 tx lanes of a half-warp)
            #pragma unroll
            for (int i = 0; i < 4; ++i) {
                float mx = fmaxf(fmaxf(s[i][0], s[i][1]), fmaxf(s[i][2], s[i][3]));
                #pragma unroll
                for (int off = 8; off > 0; off >>= 1)
                    mx = fmaxf(mx, __shfl_xor_sync(0xffffffffu, mx, off));
                const float mn = fmaxf(m_i[i], mx);
                const float corr = __expf(m_i[i] - mn);
                m_i[i] = mn;
                float rs = 0.0f;
                #pragma unroll
                for (int j = 0; j < 4; ++j) {
                    s[i][j] = __expf(s[i][j] - mn);
                    rs += s[i][j];
                }
                #pragma unroll
                for (int off = 8; off > 0; off >>= 1)
                    rs += __shfl_xor_sync(0xffffffffu, rs, off);
                l_i[i] = l_i[i] * corr + rs;
                #pragma unroll
                for (int j = 0; j < 4; ++j) o[i][j] *= corr;
            }

            // Store P transposed: Pt[c][r]
            #pragma unroll
            for (int j = 0; j < 4; ++j) {
                float4 p4;
                p4.x = s[0][j]; p4.y = s[1][j]; p4.z = s[2][j]; p4.w = s[3][j];
                *(float4*)&Pt[(4 * tx + j) * 68 + 4 * ty] = p4;
            }
            __syncthreads();

            // O += P V
            #pragma unroll 16
            for (int c = 0; c < 64; ++c) {
                const float4 pr = *(const float4*)&Pt[c * 68 + 4 * ty];
                const float4 vv = *(const float4*)&Vs[c * 68 + 4 * tx];
                const float pv[4] = {pr.x, pr.y, pr.z, pr.w};
                const float vw[4] = {vv.x, vv.y, vv.z, vv.w};
                #pragma unroll
                for (int i = 0; i < 4; ++i)
                    #pragma unroll
                    for (int j = 0; j < 4; ++j)
                        o[i][j] = fmaf(pv[i], vw[j], o[i][j]);
            }
            __syncthreads();
        }

        // Epilogue: normalize and store
        #pragma unroll
        for (int i = 0; i < 4; ++i) {
            const float inv = 1.0f / l_i[i];
            float4 r;
            r.x = o[i][0] * inv;
            r.y = o[i][1] * inv;
            r.z = o[i][2] * inv;
            r.w = o[i][3] * inv;
            *(float4*)&out[((size_t)b * SS + qb * 64 + 4 * ty + i) * HH + 4 * tx] = r;
        }
        __syncthreads();  // before next pass overwrites Qt
    }
}

// ---------------------------------------------------------------------------
extern "C" void kernel_launch(void* const* d_in, const int* in_sizes, int n_in,
                              void* d_out, int out_size)
{
    (void)in_sizes; (void)n_in; (void)out_size;
    const float* x  = (const float*)d_in[0];
    const float* Wq = (const float*)d_in[1];
    const float* Wk = (const float*)d_in[2];
    const float* Wv = (const float*)d_in[3];
    float* out = (float*)d_out;

    // QKV projection: 256 M-tiles x 3 matrices
    qkv_kernel<<<dim3(256, 3), 256>>>(x, Wq, Wk, Wv);

    // Flash attention: 32 balanced q-block pairs x 4 batches
    static int smem_set = 0;
    const int smem_bytes = 4 * 64 * 68 * sizeof(float);  // 69632
    if (!smem_set) {
        cudaFuncSetAttribute(attn_kernel,
                             cudaFuncAttributeMaxDynamicSharedMemorySize,
                             smem_bytes);
        smem_set = 1;
    }
    attn_kernel<<<dim3(32, 4), 256, smem_bytes>>>(out);
}

// round 8
// speedup vs baseline: 2.9741x; 2.9741x over previous
#include <cuda_runtime.h>
#include <cuda_bf16.h>
#include <cstdint>

#define BB 4
#define SS 4096
#define DD 1024
#define HH 64
#define NTOT 192

// bf16 hi/lo QKV scratch (written by GEMM, read by attention)
__device__ __nv_bfloat16 g_Qh[BB * SS * HH];
__device__ __nv_bfloat16 g_Ql[BB * SS * HH];
__device__ __nv_bfloat16 g_Kh[BB * SS * HH];
__device__ __nv_bfloat16 g_Kl[BB * SS * HH];
__device__ __nv_bfloat16 g_Vh[BB * SS * HH];
__device__ __nv_bfloat16 g_Vl[BB * SS * HH];
// W hi/lo, transposed to [N=192][K=1024]; Wq pre-scaled by 1/8
__device__ __nv_bfloat16 g_wh[NTOT * DD];
__device__ __nv_bfloat16 g_wl[NTOT * DD];

// ---------------------------------------------------------------------------
// Stable-PTX helpers (no tcgen05 — harness targets compute_103, not 103a)
// ---------------------------------------------------------------------------
__device__ __forceinline__ uint32_t smem_u32(const void* p) {
    uint32_t a;
    asm("{ .reg .u64 t; cvta.to.shared.u64 t, %1; cvt.u32.u64 %0, t; }" : "=r"(a) : "l"(p));
    return a;
}
__device__ __forceinline__ void mma_bf16(float* c, const uint32_t* a, const uint32_t* b) {
    asm volatile(
        "mma.sync.aligned.m16n8k16.row.col.f32.bf16.bf16.f32 "
        "{%0,%1,%2,%3}, {%4,%5,%6,%7}, {%8,%9}, {%0,%1,%2,%3};"
        : "+f"(c[0]), "+f"(c[1]), "+f"(c[2]), "+f"(c[3])
        : "r"(a[0]), "r"(a[1]), "r"(a[2]), "r"(a[3]), "r"(b[0]), "r"(b[1]));
}
__device__ __forceinline__ void ldsm_x4(uint32_t* r, uint32_t addr) {
    asm volatile("ldmatrix.sync.aligned.m8n8.x4.shared.b16 {%0,%1,%2,%3}, [%4];"
                 : "=r"(r[0]), "=r"(r[1]), "=r"(r[2]), "=r"(r[3]) : "r"(addr));
}
__device__ __forceinline__ void ldsm_x4_t(uint32_t* r, uint32_t addr) {
    asm volatile("ldmatrix.sync.aligned.m8n8.x4.trans.shared.b16 {%0,%1,%2,%3}, [%4];"
                 : "=r"(r[0]), "=r"(r[1]), "=r"(r[2]), "=r"(r[3]) : "r"(addr));
}
__device__ __forceinline__ uint32_t pack_bf16(float lo, float hi) {
    uint32_t r;
    asm("cvt.rn.bf16x2.f32 %0, %1, %2;" : "=r"(r) : "f"(hi), "f"(lo));
    return r;
}
// v = hi + lo split of a float pair (x -> low half, y -> high half)
__device__ __forceinline__ void split2(float x, float y, uint32_t& hi, uint32_t& lo) {
    hi = pack_bf16(x, y);
    float hx = __uint_as_float(hi << 16);
    float hy = __uint_as_float(hi & 0xffff0000u);
    lo = pack_bf16(x - hx, y - hy);
}
#define CP_ASYNC16(dst, src) \
    asm volatile("cp.async.cg.shared.global [%0], [%1], 16;" :: "r"(dst), "l"(src) : "memory")
#define CP_COMMIT() asm volatile("cp.async.commit_group;" ::: "memory")
#define CP_WAIT0()  asm volatile("cp.async.wait_group 0;" ::: "memory")

// ---------------------------------------------------------------------------
// wconv: W fp32 [1024,64] x3 -> hi/lo bf16 [192,1024], Wq scaled by 0.125
// ---------------------------------------------------------------------------
__global__ void wconv_kernel(const float* __restrict__ Wq,
                             const float* __restrict__ Wk,
                             const float* __restrict__ Wv)
{
    int i = blockIdx.x * 256 + threadIdx.x;
    if (i >= NTOT * DD) return;
    int n = i / DD, k = i - n * DD;
    int t = n >> 6, h = n & 63;
    const float* W = (t == 0) ? Wq : ((t == 1) ? Wk : Wv);
    float v = W[(size_t)k * HH + h] * ((t == 0) ? 0.125f : 1.0f);
    __nv_bfloat16 hi = __float2bfloat16(v);
    g_wh[i] = hi;
    g_wl[i] = __float2bfloat16(v - __bfloat162float(hi));
}

// ---------------------------------------------------------------------------
// QKV GEMM: C[16384,192] = x * W^T via split-bf16 HMMA.
// BM=64, BN=192(full), KC=64; 256 threads = 8 warps (2 m x 4 n), warp = 32r x 48c.
// smem per stage: Ah|Al [64][72], Bh|Bl [192][72]; double buffered.
// ---------------------------------------------------------------------------
#define G_STG   73728
#define G_AH    0
#define G_AL    9216
#define G_BH    18432
#define G_BL    46080

__global__ __launch_bounds__(256, 1) void qkv_mma_kernel(const float* __restrict__ x)
{
    extern __shared__ char smem[];
    const uint32_t sm0 = smem_u32(smem);
    const int tid = threadIdx.x;
    const int wid = tid >> 5, lane = tid & 31;
    const int wm = wid & 1, wn = wid >> 1;          // warp: rows wm*32, cols wn*48
    const int m0 = blockIdx.x * 64;

    const int li  = lane & 7;
    const int r16 = lane & 15;
    const int hfA = (lane >> 4) * 16;               // A-frag col-half bytes
    const int nh8 = ((lane >> 4) & 1) * 8;          // B-frag n-half rows
    const int kh16 = ((lane >> 3) & 1) * 16;        // B-frag k-half bytes

    float acc[2][6][4];
    #pragma unroll
    for (int mi = 0; mi < 2; ++mi)
        #pragma unroll
        for (int j = 0; j < 6; ++j)
            #pragma unroll
            for (int q = 0; q < 4; ++q) acc[mi][j][q] = 0.0f;

    const int ar  = tid >> 2;                       // A loader row 0..63
    const int ac0 = (tid & 3) * 16;                 // A loader col base

    float4 av[4];
    // ---- prologue: chunk 0 ----
    {
        const float* ap = x + (size_t)(m0 + ar) * DD + ac0;
        #pragma unroll
        for (int i = 0; i < 4; ++i) av[i] = *(const float4*)(ap + 4 * i);
        #pragma unroll
        for (int i = 0; i < 6; ++i) {
            int id = tid + 256 * i, row = id >> 3, ch = id & 7;
            CP_ASYNC16(sm0 + G_BH + row * 144 + ch * 16, g_wh + (size_t)row * DD + ch * 8);
            CP_ASYNC16(sm0 + G_BL + row * 144 + ch * 16, g_wl + (size_t)row * DD + ch * 8);
        }
        CP_COMMIT();
        char* st = smem;
        #pragma unroll
        for (int i = 0; i < 4; ++i) {
            uint32_t h0, l0, h1, l1;
            split2(av[i].x, av[i].y, h0, l0);
            split2(av[i].z, av[i].w, h1, l1);
            uint2 hv = {h0, h1}, lv = {l0, l1};
            *(uint2*)(st + G_AH + ar * 144 + ac0 * 2 + i * 8) = hv;
            *(uint2*)(st + G_AL + ar * 144 + ac0 * 2 + i * 8) = lv;
        }
        CP_WAIT0();
        __syncthreads();
    }

    for (int c = 0; c < 16; ++c) {
        const int s = c & 1;
        const uint32_t sb = sm0 + s * G_STG;

        if (c < 15) {   // prefetch chunk c+1 into the other stage
            const float* ap = x + (size_t)(m0 + ar) * DD + (c + 1) * 64 + ac0;
            #pragma unroll
            for (int i = 0; i < 4; ++i) av[i] = *(const float4*)(ap + 4 * i);
            const uint32_t ob = sm0 + (s ^ 1) * G_STG;
            #pragma unroll
            for (int i = 0; i < 6; ++i) {
                int id = tid + 256 * i, row = id >> 3, ch = id & 7;
                CP_ASYNC16(ob + G_BH + row * 144 + ch * 16,
                           g_wh + (size_t)row * DD + (c + 1) * 64 + ch * 8);
                CP_ASYNC16(ob + G_BL + row * 144 + ch * 16,
                           g_wl + (size_t)row * DD + (c + 1) * 64 + ch * 8);
            }
            CP_COMMIT();
        }

        // ---- consume stage s: 4 k16-steps ----
        #pragma unroll
        for (int kk = 0; kk < 4; ++kk) {
            uint32_t Ah[2][4], Al[2][4];
            #pragma unroll
            for (int mi = 0; mi < 2; ++mi) {
                uint32_t a = sb + (wm * 32 + mi * 16 + r16) * 144 + kk * 32 + hfA;
                ldsm_x4(Ah[mi], a + G_AH);
                ldsm_x4(Al[mi], a + G_AL);
            }
            uint32_t Bh[6][2], Bl[6][2];
            #pragma unroll
            for (int j2 = 0; j2 < 3; ++j2) {
                uint32_t a = sb + (wn * 48 + j2 * 16 + li + nh8) * 144 + kk * 32 + kh16;
                ldsm_x4(&Bh[2 * j2][0], a + G_BH);
                ldsm_x4(&Bl[2 * j2][0], a + G_BL);
            }
            #pragma unroll
            for (int mi = 0; mi < 2; ++mi)
                #pragma unroll
                for (int j = 0; j < 6; ++j) {
                    mma_bf16(acc[mi][j], Ah[mi], Bh[j]);
                    mma_bf16(acc[mi][j], Ah[mi], Bl[j]);
                    mma_bf16(acc[mi][j], Al[mi], Bh[j]);
                }
        }

        if (c < 15) {   // store converted A into the other stage
            char* st = smem + (s ^ 1) * G_STG;
            #pragma unroll
            for (int i = 0; i < 4; ++i) {
                uint32_t h0, l0, h1, l1;
                split2(av[i].x, av[i].y, h0, l0);
                split2(av[i].z, av[i].w, h1, l1);
                uint2 hv = {h0, h1}, lv = {l0, l1};
                *(uint2*)(st + G_AH + ar * 144 + ac0 * 2 + i * 8) = hv;
                *(uint2*)(st + G_AL + ar * 144 + ac0 * 2 + i * 8) = lv;
            }
        }
        CP_WAIT0();
        __syncthreads();
    }

    // ---- epilogue: split fp32 acc -> hi/lo bf16 into Q/K/V ----
    const int g = lane >> 2, t2 = (lane & 3) * 2;
    #pragma unroll
    for (int mi = 0; mi < 2; ++mi) {
        #pragma unroll
        for (int j = 0; j < 6; ++j) {
            const int nG = wn * 48 + j * 8 + t2;
            const int tns = nG >> 6, h = nG & 63;
            __nv_bfloat16* hp = (tns == 0) ? g_Qh : ((tns == 1) ? g_Kh : g_Vh);
            __nv_bfloat16* lp = (tns == 0) ? g_Ql : ((tns == 1) ? g_Kl : g_Vl);
            const int rowA = m0 + wm * 32 + mi * 16 + g;
            uint32_t hi, lo;
            split2(acc[mi][j][0], acc[mi][j][1], hi, lo);
            *(uint32_t*)&hp[(size_t)rowA * HH + h] = hi;
            *(uint32_t*)&lp[(size_t)rowA * HH + h] = lo;
            split2(acc[mi][j][2], acc[mi][j][3], hi, lo);
            *(uint32_t*)&hp[(size_t)(rowA + 8) * HH + h] = hi;
            *(uint32_t*)&lp[(size_t)(rowA + 8) * HH + h] = lo;
        }
    }
}

// ---------------------------------------------------------------------------
// Attention: causal flash, split-bf16 HMMA. grid (32,4): CTA handles q-blocks
// {p, 63-p} (65 tiles, balanced). 128 threads = 4 warps, warp = 16 q-rows.
// S and O live in mma fragments; P converts frag->frag (no smem round-trip).
// ---------------------------------------------------------------------------
#define A_QH 0
#define A_QL 9216
#define A_ST0 18432      // stage base; per stage: Kh|Kl|Vh|Vl each 9216
#define A_STG 36864
#define A_KH 0
#define A_KL 9216
#define A_VH 18432
#define A_VL 27648

__global__ __launch_bounds__(128, 1) void attn_mma_kernel(float* __restrict__ out)
{
    extern __shared__ char smem[];
    const uint32_t sm0 = smem_u32(smem);
    const int b = blockIdx.y, pid = blockIdx.x;
    const int tid = threadIdx.x;
    const int w = tid >> 5, lane = tid & 31;

    const int li   = lane & 7;
    const int r16  = lane & 15;
    const int hfA  = (lane >> 4) * 16;
    const int nh8  = ((lane >> 4) & 1) * 8;
    const int kh16 = ((lane >> 3) & 1) * 16;
    const int sh8  = ((lane >> 3) & 1) * 8;      // V-trans s-half
    const int hh16 = ((lane >> 4) & 1) * 16;     // V-trans h-half bytes
    const int g = lane >> 2, t2 = (lane & 3) * 2;

    const size_t base = (size_t)b * SS * HH;

    for (int pass = 0; pass < 2; ++pass) {
        const int qb = pass ? (63 - pid) : pid;

        // prefetch K/V tile kb=0 into stage 0
        {
            const uint32_t ob = sm0 + A_ST0;
            const size_t kvo = base + (size_t)0 * HH;
            #pragma unroll
            for (int i = 0; i < 16; ++i) {
                int id = tid + 128 * i;          // 2048 chunks: arr(4) x row(64) x ch(8)
                int arr = id >> 9, rem = id & 511, row = rem >> 3, ch = rem & 7;
                const __nv_bfloat16* src =
                    (arr == 0) ? g_Kh : (arr == 1) ? g_Kl : (arr == 2) ? g_Vh : g_Vl;
                CP_ASYNC16(ob + arr * 9216 + row * 144 + ch * 16,
                           src + kvo + (size_t)row * HH + ch * 8);
            }
            CP_COMMIT();
        }
        // load Q tile hi/lo (regular 16B loads)
        {
            const size_t qo = base + (size_t)qb * 64 * HH;
            #pragma unroll
            for (int i = 0; i < 8; ++i) {
                int id = tid + 128 * i;          // 1024 chunks: arr(2) x row(64) x ch(8)
                int arr = id >> 9, rem = id & 511, row = rem >> 3, ch = rem & 7;
                const __nv_bfloat16* src = arr ? g_Ql : g_Qh;
                *(uint4*)(smem + arr * 9216 + row * 144 + ch * 16) =
                    *(const uint4*)(src + qo + (size_t)row * HH + ch * 8);
            }
        }
        CP_WAIT0();
        __syncthreads();

        // extract Q fragments (4 k-steps x hi/lo), Q smem not touched again
        uint32_t qh[4][4], ql[4][4];
        #pragma unroll
        for (int kk = 0; kk < 4; ++kk) {
            uint32_t a = sm0 + (w * 16 + r16) * 144 + kk * 32 + hfA;
            ldsm_x4(qh[kk], a + A_QH);
            ldsm_x4(ql[kk], a + A_QL);
        }

        float O[8][4];
        float m_[2] = {-1e30f, -1e30f}, l_[2] = {0.0f, 0.0f};
        #pragma unroll
        for (int j = 0; j < 8; ++j)
            #pragma unroll
            for (int q = 0; q < 4; ++q) O[j][q] = 0.0f;

        for (int kb = 0; kb <= qb; ++kb) {
            const int s = kb & 1;
            const uint32_t sb = sm0 + A_ST0 + s * A_STG;

            if (kb < qb) {   // prefetch next tile
                const uint32_t ob = sm0 + A_ST0 + (s ^ 1) * A_STG;
                const size_t kvo = base + (size_t)(kb + 1) * 64 * HH;
                #pragma unroll
                for (int i = 0; i < 16; ++i) {
                    int id = tid + 128 * i;
                    int arr = id >> 9, rem = id & 511, row = rem >> 3, ch = rem & 7;
                    const __nv_bfloat16* src =
                        (arr == 0) ? g_Kh : (arr == 1) ? g_Kl : (arr == 2) ? g_Vh : g_Vl;
                    CP_ASYNC16(ob + arr * 9216 + row * 144 + ch * 16,
                               src + kvo + (size_t)row * HH + ch * 8);
                }
                CP_COMMIT();
            }

            // ---- S = (Qh+Ql)(Kh+Kl)^T, 3 terms ----
            float S[8][4];
            #pragma unroll
            for (int j = 0; j < 8; ++j)
                #pragma unroll
                for (int q = 0; q < 4; ++q) S[j][q] = 0.0f;

            #pragma unroll
            for (int kk = 0; kk < 4; ++kk) {
                uint32_t Kh[8][2], Kl[8][2];
                #pragma unroll
                for (int n2 = 0; n2 < 4; ++n2) {
                    uint32_t a = sb + (n2 * 16 + li + nh8) * 144 + kk * 32 + kh16;
                    ldsm_x4(&Kh[2 * n2][0], a + A_KH);
                    ldsm_x4(&Kl[2 * n2][0], a + A_KL);
                }
                #pragma unroll
                for (int j = 0; j < 8; ++j) {
                    mma_bf16(S[j], qh[kk], Kh[j]);
                    mma_bf16(S[j], qh[kk], Kl[j]);
                    mma_bf16(S[j], ql[kk], Kh[j]);
                }
            }

            // causal mask on diagonal tile (local coords suffice)
            if (kb == qb) {
                const int rA = w * 16 + g, rB = rA + 8;
                #pragma unroll
                for (int j = 0; j < 8; ++j) {
                    const int c0 = j * 8 + t2;
                    if (c0 > rA)     S[j][0] = -1e30f;
                    if (c0 + 1 > rA) S[j][1] = -1e30f;
                    if (c0 > rB)     S[j][2] = -1e30f;
                    if (c0 + 1 > rB) S[j][3] = -1e30f;
                }
            }

            // ---- online softmax (rows g and g+8) ----
            #pragma unroll
            for (int hf = 0; hf < 2; ++hf) {
                const int c0 = 2 * hf;
                float mx = fmaxf(S[0][c0], S[0][c0 + 1]);
                #pragma unroll
                for (int j = 1; j < 8; ++j)
                    mx = fmaxf(mx, fmaxf(S[j][c0], S[j][c0 + 1]));
                mx = fmaxf(mx, __shfl_xor_sync(0xffffffffu, mx, 1));
                mx = fmaxf(mx, __shfl_xor_sync(0xffffffffu, mx, 2));
                const float mn = fmaxf(m_[hf], mx);
                const float corr = __expf(m_[hf] - mn);
                m_[hf] = mn;
                float rs = 0.0f;
                #pragma unroll
                for (int j = 0; j < 8; ++j) {
                    float e0 = __expf(S[j][c0] - mn);
                    float e1 = __expf(S[j][c0 + 1] - mn);
                    S[j][c0] = e0; S[j][c0 + 1] = e1;
                    rs += e0 + e1;
                }
                rs += __shfl_xor_sync(0xffffffffu, rs, 1);
                rs += __shfl_xor_sync(0xffffffffu, rs, 2);
                l_[hf] = l_[hf] * corr + rs;
                #pragma unroll
                for (int j = 0; j < 8; ++j) { O[j][c0] *= corr; O[j][c0 + 1] *= corr; }
            }

            // ---- O += (Ph+Pl)(Vh+Vl), 3 terms; P frag built from S frags ----
            #pragma unroll
            for (int kk = 0; kk < 4; ++kk) {
                uint32_t ph[4], pl[4];
                {
                    const int jA = 2 * kk, jB = jA + 1;
                    split2(S[jA][0], S[jA][1], ph[0], pl[0]);
                    split2(S[jA][2], S[jA][3], ph[1], pl[1]);
                    split2(S[jB][0], S[jB][1], ph[2], pl[2]);
                    split2(S[jB][2], S[jB][3], ph[3], pl[3]);
                }
                uint32_t Vh[8][2], Vl[8][2];
                #pragma unroll
                for (int h2 = 0; h2 < 4; ++h2) {
                    uint32_t a = sb + (kk * 16 + li + sh8) * 144 + h2 * 32 + hh16;
                    ldsm_x4_t(&Vh[2 * h2][0], a + A_VH);
                    ldsm_x4_t(&Vl[2 * h2][0], a + A_VL);
                }
                #pragma unroll
                for (int j = 0; j < 8; ++j) {
                    mma_bf16(O[j], ph, Vh[j]);
                    mma_bf16(O[j], ph, Vl[j]);
                    mma_bf16(O[j], pl, Vh[j]);
                }
            }

            CP_WAIT0();
            __syncthreads();
        }

        // ---- epilogue ----
        const float iA = 1.0f / l_[0], iB = 1.0f / l_[1];
        const int rowA = qb * 64 + w * 16 + g;
        float* ob = out + (size_t)b * SS * HH;
        #pragma unroll
        for (int j = 0; j < 8; ++j) {
            const int col = j * 8 + t2;
            float2 v0 = {O[j][0] * iA, O[j][1] * iA};
            float2 v1 = {O[j][2] * iB, O[j][3] * iB};
            *(float2*)&ob[(size_t)rowA * HH + col] = v0;
            *(float2*)&ob[(size_t)(rowA + 8) * HH + col] = v1;
        }
        __syncthreads();   // before next pass overwrites Q smem / stage 0
    }
}

// ---------------------------------------------------------------------------
extern "C" void kernel_launch(void* const* d_in, const int* in_sizes, int n_in,
                              void* d_out, int out_size)
{
    (void)in_sizes; (void)n_in; (void)out_size;
    const float* x  = (const float*)d_in[0];
    const float* Wq = (const float*)d_in[1];
    const float* Wk = (const float*)d_in[2];
    const float* Wv = (const float*)d_in[3];
    float* out = (float*)d_out;

    static int attr_set = 0;
    const int gemm_smem = 2 * G_STG;                // 147456
    const int attn_smem = A_ST0 + 2 * A_STG;        // 92160
    if (!attr_set) {
        cudaFuncSetAttribute(qkv_mma_kernel,
                             cudaFuncAttributeMaxDynamicSharedMemorySize, gemm_smem);
        cudaFuncSetAttribute(attn_mma_kernel,
                             cudaFuncAttributeMaxDynamicSharedMemorySize, attn_smem);
        attr_set = 1;
    }

    wconv_kernel<<<(NTOT * DD + 255) / 256, 256>>>(Wq, Wk, Wv);
    qkv_mma_kernel<<<SS * BB / 64, 256, gemm_smem>>>(x);
    attn_mma_kernel<<<dim3(32, 4), 128, attn_smem>>>(out);
}

// round 9
// speedup vs baseline: 3.5031x; 1.1779x over previous
#include <cuda_runtime.h>
#include <cuda_bf16.h>
#include <cuda_fp16.h>
#include <cstdint>

#define BB 4
#define SS 4096
#define DD 1024
#define HH 64
#define NTOT 192

// bf16 hi/lo Q,K scratch; V in single fp16 (PV product is single-term fp16).
__device__ __nv_bfloat16 g_Qh[BB * SS * HH];
__device__ __nv_bfloat16 g_Ql[BB * SS * HH];
__device__ __nv_bfloat16 g_Kh[BB * SS * HH];
__device__ __nv_bfloat16 g_Kl[BB * SS * HH];
__device__ __half        g_V16[BB * SS * HH];
// W hi/lo, transposed to [N=192][K=1024]; Wq pre-scaled by 0.125*log2(e)
__device__ __nv_bfloat16 g_wh[NTOT * DD];
__device__ __nv_bfloat16 g_wl[NTOT * DD];

// ---------------------------------------------------------------------------
// Stable-PTX helpers (harness emits compute_103 PTX: no tcgen05 allowed)
// ---------------------------------------------------------------------------
__device__ __forceinline__ uint32_t smem_u32(const void* p) {
    uint32_t a;
    asm("{ .reg .u64 t; cvta.to.shared.u64 t, %1; cvt.u32.u64 %0, t; }" : "=r"(a) : "l"(p));
    return a;
}
__device__ __forceinline__ void mma_bf16(float* c, const uint32_t* a, const uint32_t* b) {
    asm volatile(
        "mma.sync.aligned.m16n8k16.row.col.f32.bf16.bf16.f32 "
        "{%0,%1,%2,%3}, {%4,%5,%6,%7}, {%8,%9}, {%0,%1,%2,%3};"
        : "+f"(c[0]), "+f"(c[1]), "+f"(c[2]), "+f"(c[3])
        : "r"(a[0]), "r"(a[1]), "r"(a[2]), "r"(a[3]), "r"(b[0]), "r"(b[1]));
}
__device__ __forceinline__ void mma_f16(float* c, const uint32_t* a, const uint32_t* b) {
    asm volatile(
        "mma.sync.aligned.m16n8k16.row.col.f32.f16.f16.f32 "
        "{%0,%1,%2,%3}, {%4,%5,%6,%7}, {%8,%9}, {%0,%1,%2,%3};"
        : "+f"(c[0]), "+f"(c[1]), "+f"(c[2]), "+f"(c[3])
        : "r"(a[0]), "r"(a[1]), "r"(a[2]), "r"(a[3]), "r"(b[0]), "r"(b[1]));
}
__device__ __forceinline__ void ldsm_x4(uint32_t* r, uint32_t addr) {
    asm volatile("ldmatrix.sync.aligned.m8n8.x4.shared.b16 {%0,%1,%2,%3}, [%4];"
                 : "=r"(r[0]), "=r"(r[1]), "=r"(r[2]), "=r"(r[3]) : "r"(addr));
}
__device__ __forceinline__ void ldsm_x4_t(uint32_t* r, uint32_t addr) {
    asm volatile("ldmatrix.sync.aligned.m8n8.x4.trans.shared.b16 {%0,%1,%2,%3}, [%4];"
                 : "=r"(r[0]), "=r"(r[1]), "=r"(r[2]), "=r"(r[3]) : "r"(addr));
}
__device__ __forceinline__ uint32_t pack_bf16(float lo, float hi) {
    uint32_t r;
    asm("cvt.rn.bf16x2.f32 %0, %1, %2;" : "=r"(r) : "f"(hi), "f"(lo));
    return r;
}
__device__ __forceinline__ uint32_t pack_h2(float lo, float hi) {   // lo -> low half
    uint32_t r;
    asm("cvt.rn.f16x2.f32 %0, %1, %2;" : "=r"(r) : "f"(hi), "f"(lo));
    return r;
}
__device__ __forceinline__ uint32_t ex2_h2(uint32_t h2) {
    uint32_t r;
    asm("ex2.approx.f16x2 %0, %1;" : "=r"(r) : "r"(h2));
    return r;
}
__device__ __forceinline__ float ex2f(float x) {
    float r;
    asm("ex2.approx.f32 %0, %1;" : "=f"(r) : "f"(x));
    return r;
}
// v = hi + lo bf16 split of a float pair (x -> low half, y -> high half)
__device__ __forceinline__ void split2(float x, float y, uint32_t& hi, uint32_t& lo) {
    hi = pack_bf16(x, y);
    float hx = __uint_as_float(hi << 16);
    float hy = __uint_as_float(hi & 0xffff0000u);
    lo = pack_bf16(x - hx, y - hy);
}
#define CP_ASYNC16(dst, src) \
    asm volatile("cp.async.cg.shared.global [%0], [%1], 16;" :: "r"(dst), "l"(src) : "memory")
#define CP_COMMIT() asm volatile("cp.async.commit_group;" ::: "memory")
#define CP_WAIT0()  asm volatile("cp.async.wait_group 0;" ::: "memory")

// ---------------------------------------------------------------------------
// wconv: W fp32 [1024,64] x3 -> hi/lo bf16 [192,1024].
// Wq scaled by 0.125*log2(e) so attention scores are in log2 domain (exp2 softmax).
// ---------------------------------------------------------------------------
__global__ void wconv_kernel(const float* __restrict__ Wq,
                             const float* __restrict__ Wk,
                             const float* __restrict__ Wv)
{
    int i = blockIdx.x * 256 + threadIdx.x;
    if (i >= NTOT * DD) return;
    int n = i / DD, k = i - n * DD;
    int t = n >> 6, h = n & 63;
    const float* W = (t == 0) ? Wq : ((t == 1) ? Wk : Wv);
    float v = W[(size_t)k * HH + h] * ((t == 0) ? 0.125f * 1.4426950408889634f : 1.0f);
    __nv_bfloat16 hi = __float2bfloat16(v);
    g_wh[i] = hi;
    g_wl[i] = __float2bfloat16(v - __bfloat162float(hi));
}

// ---------------------------------------------------------------------------
// QKV GEMM: C[16384,192] = x * W^T via split-bf16 HMMA (3 terms).
// BM=64, BN=192, KC=64; 256 threads = 8 warps (2m x 4n), warp = 32r x 48c.
// Epilogue: Q,K -> hi/lo bf16; V -> fp16.
// ---------------------------------------------------------------------------
#define G_STG   73728
#define G_AH    0
#define G_AL    9216
#define G_BH    18432
#define G_BL    46080

__global__ __launch_bounds__(256, 1) void qkv_mma_kernel(const float* __restrict__ x)
{
    extern __shared__ char smem[];
    const uint32_t sm0 = smem_u32(smem);
    const int tid = threadIdx.x;
    const int wid = tid >> 5, lane = tid & 31;
    const int wm = wid & 1, wn = wid >> 1;
    const int m0 = blockIdx.x * 64;

    const int li  = lane & 7;
    const int r16 = lane & 15;
    const int hfA = (lane >> 4) * 16;
    const int nh8 = ((lane >> 4) & 1) * 8;
    const int kh16 = ((lane >> 3) & 1) * 16;

    float acc[2][6][4];
    #pragma unroll
    for (int mi = 0; mi < 2; ++mi)
        #pragma unroll
        for (int j = 0; j < 6; ++j)
            #pragma unroll
            for (int q = 0; q < 4; ++q) acc[mi][j][q] = 0.0f;

    const int ar  = tid >> 2;
    const int ac0 = (tid & 3) * 16;

    float4 av[4];
    // ---- prologue: chunk 0 ----
    {
        const float* ap = x + (size_t)(m0 + ar) * DD + ac0;
        #pragma unroll
        for (int i = 0; i < 4; ++i) av[i] = *(const float4*)(ap + 4 * i);
        #pragma unroll
        for (int i = 0; i < 6; ++i) {
            int id = tid + 256 * i, row = id >> 3, ch = id & 7;
            CP_ASYNC16(sm0 + G_BH + row * 144 + ch * 16, g_wh + (size_t)row * DD + ch * 8);
            CP_ASYNC16(sm0 + G_BL + row * 144 + ch * 16, g_wl + (size_t)row * DD + ch * 8);
        }
        CP_COMMIT();
        char* st = smem;
        #pragma unroll
        for (int i = 0; i < 4; ++i) {
            uint32_t h0, l0, h1, l1;
            split2(av[i].x, av[i].y, h0, l0);
            split2(av[i].z, av[i].w, h1, l1);
            uint2 hv = {h0, h1}, lv = {l0, l1};
            *(uint2*)(st + G_AH + ar * 144 + ac0 * 2 + i * 8) = hv;
            *(uint2*)(st + G_AL + ar * 144 + ac0 * 2 + i * 8) = lv;
        }
        CP_WAIT0();
        __syncthreads();
    }

    for (int c = 0; c < 16; ++c) {
        const int s = c & 1;
        const uint32_t sb = sm0 + s * G_STG;

        if (c < 15) {
            const float* ap = x + (size_t)(m0 + ar) * DD + (c + 1) * 64 + ac0;
            #pragma unroll
            for (int i = 0; i < 4; ++i) av[i] = *(const float4*)(ap + 4 * i);
            const uint32_t ob = sm0 + (s ^ 1) * G_STG;
            #pragma unroll
            for (int i = 0; i < 6; ++i) {
                int id = tid + 256 * i, row = id >> 3, ch = id & 7;
                CP_ASYNC16(ob + G_BH + row * 144 + ch * 16,
                           g_wh + (size_t)row * DD + (c + 1) * 64 + ch * 8);
                CP_ASYNC16(ob + G_BL + row * 144 + ch * 16,
                           g_wl + (size_t)row * DD + (c + 1) * 64 + ch * 8);
            }
            CP_COMMIT();
        }

        #pragma unroll
        for (int kk = 0; kk < 4; ++kk) {
            uint32_t Ah[2][4], Al[2][4];
            #pragma unroll
            for (int mi = 0; mi < 2; ++mi) {
                uint32_t a = sb + (wm * 32 + mi * 16 + r16) * 144 + kk * 32 + hfA;
                ldsm_x4(Ah[mi], a + G_AH);
                ldsm_x4(Al[mi], a + G_AL);
            }
            uint32_t Bh[6][2], Bl[6][2];
            #pragma unroll
            for (int j2 = 0; j2 < 3; ++j2) {
                uint32_t a = sb + (wn * 48 + j2 * 16 + li + nh8) * 144 + kk * 32 + kh16;
                ldsm_x4(&Bh[2 * j2][0], a + G_BH);
                ldsm_x4(&Bl[2 * j2][0], a + G_BL);
            }
            #pragma unroll
            for (int mi = 0; mi < 2; ++mi)
                #pragma unroll
                for (int j = 0; j < 6; ++j) {
                    mma_bf16(acc[mi][j], Ah[mi], Bh[j]);
                    mma_bf16(acc[mi][j], Ah[mi], Bl[j]);
                    mma_bf16(acc[mi][j], Al[mi], Bh[j]);
                }
        }

        if (c < 15) {
            char* st = smem + (s ^ 1) * G_STG;
            #pragma unroll
            for (int i = 0; i < 4; ++i) {
                uint32_t h0, l0, h1, l1;
                split2(av[i].x, av[i].y, h0, l0);
                split2(av[i].z, av[i].w, h1, l1);
                uint2 hv = {h0, h1}, lv = {l0, l1};
                *(uint2*)(st + G_AH + ar * 144 + ac0 * 2 + i * 8) = hv;
                *(uint2*)(st + G_AL + ar * 144 + ac0 * 2 + i * 8) = lv;
            }
        }
        CP_WAIT0();
        __syncthreads();
    }

    // ---- epilogue: Q,K -> hi/lo bf16; V -> fp16 ----
    const int g = lane >> 2, t2 = (lane & 3) * 2;
    #pragma unroll
    for (int mi = 0; mi < 2; ++mi) {
        #pragma unroll
        for (int j = 0; j < 6; ++j) {
            const int nG = wn * 48 + j * 8 + t2;
            const int tns = nG >> 6, h = nG & 63;
            const int rowA = m0 + wm * 32 + mi * 16 + g;
            if (tns == 2) {
                *(uint32_t*)&g_V16[(size_t)rowA * HH + h] =
                    pack_h2(acc[mi][j][0], acc[mi][j][1]);
                *(uint32_t*)&g_V16[(size_t)(rowA + 8) * HH + h] =
                    pack_h2(acc[mi][j][2], acc[mi][j][3]);
            } else {
                __nv_bfloat16* hp = (tns == 0) ? g_Qh : g_Kh;
                __nv_bfloat16* lp = (tns == 0) ? g_Ql : g_Kl;
                uint32_t hi, lo;
                split2(acc[mi][j][0], acc[mi][j][1], hi, lo);
                *(uint32_t*)&hp[(size_t)rowA * HH + h] = hi;
                *(uint32_t*)&lp[(size_t)rowA * HH + h] = lo;
                split2(acc[mi][j][2], acc[mi][j][3], hi, lo);
                *(uint32_t*)&hp[(size_t)(rowA + 8) * HH + h] = hi;
                *(uint32_t*)&lp[(size_t)(rowA + 8) * HH + h] = lo;
            }
        }
    }
}

// ---------------------------------------------------------------------------
// Attention: causal flash. QK = 3-term bf16 HMMA (log2-domain scores);
// softmax via ex2.f16x2 producing fp16 P fragments directly; PV = 1-term fp16.
// grid (32,4): CTA handles q-blocks {p, 63-p} (65 tiles, balanced).
// ---------------------------------------------------------------------------
#define A_QH 0
#define A_QL 9216
#define A_ST0 18432      // per stage: Kh | Kl | V(fp16), each 9216
#define A_STG 27648
#define A_KH 0
#define A_KL 9216
#define A_V  18432

__global__ __launch_bounds__(128, 1) void attn_mma_kernel(float* __restrict__ out)
{
    extern __shared__ char smem[];
    const uint32_t sm0 = smem_u32(smem);
    const int b = blockIdx.y, pid = blockIdx.x;
    const int tid = threadIdx.x;
    const int w = tid >> 5, lane = tid & 31;

    const int li   = lane & 7;
    const int r16  = lane & 15;
    const int hfA  = (lane >> 4) * 16;
    const int nh8  = ((lane >> 4) & 1) * 8;
    const int kh16 = ((lane >> 3) & 1) * 16;
    const int sh8  = ((lane >> 3) & 1) * 8;
    const int hh16 = ((lane >> 4) & 1) * 16;
    const int g = lane >> 2, t2 = (lane & 3) * 2;

    const size_t base = (size_t)b * SS * HH;

    for (int pass = 0; pass < 2; ++pass) {
        const int qb = pass ? (63 - pid) : pid;

        // prefetch K/V tile kb=0 into stage 0 (Kh, Kl bf16; V fp16)
        {
            const uint32_t ob = sm0 + A_ST0;
            #pragma unroll
            for (int i = 0; i < 12; ++i) {
                int id = tid + 128 * i;          // 1536 chunks: arr(3) x row(64) x ch(8)
                int arr = id >> 9, rem = id & 511, row = rem >> 3, ch = rem & 7;
                const char* src =
                    (arr == 0) ? (const char*)(g_Kh + base + (size_t)row * HH + ch * 8)
                  : (arr == 1) ? (const char*)(g_Kl + base + (size_t)row * HH + ch * 8)
                               : (const char*)(g_V16 + base + (size_t)row * HH + ch * 8);
                CP_ASYNC16(ob + arr * 9216 + row * 144 + ch * 16, src);
            }
            CP_COMMIT();
        }
        // load Q tile hi/lo
        {
            const size_t qo = base + (size_t)qb * 64 * HH;
            #pragma unroll
            for (int i = 0; i < 8; ++i) {
                int id = tid + 128 * i;
                int arr = id >> 9, rem = id & 511, row = rem >> 3, ch = rem & 7;
                const __nv_bfloat16* src = arr ? g_Ql : g_Qh;
                *(uint4*)(smem + arr * 9216 + row * 144 + ch * 16) =
                    *(const uint4*)(src + qo + (size_t)row * HH + ch * 8);
            }
        }
        CP_WAIT0();
        __syncthreads();

        uint32_t qh[4][4], ql[4][4];
        #pragma unroll
        for (int kk = 0; kk < 4; ++kk) {
            uint32_t a = sm0 + (w * 16 + r16) * 144 + kk * 32 + hfA;
            ldsm_x4(qh[kk], a + A_QH);
            ldsm_x4(ql[kk], a + A_QL);
        }

        float O[8][4];
        float m_[2] = {-1e30f, -1e30f}, l_[2] = {0.0f, 0.0f};
        #pragma unroll
        for (int j = 0; j < 8; ++j)
            #pragma unroll
            for (int q = 0; q < 4; ++q) O[j][q] = 0.0f;

        for (int kb = 0; kb <= qb; ++kb) {
            const int s = kb & 1;
            const uint32_t sb = sm0 + A_ST0 + s * A_STG;

            if (kb < qb) {
                const uint32_t ob = sm0 + A_ST0 + (s ^ 1) * A_STG;
                const size_t kvo = base + (size_t)(kb + 1) * 64 * HH;
                #pragma unroll
                for (int i = 0; i < 12; ++i) {
                    int id = tid + 128 * i;
                    int arr = id >> 9, rem = id & 511, row = rem >> 3, ch = rem & 7;
                    const char* src =
                        (arr == 0) ? (const char*)(g_Kh + kvo + (size_t)row * HH + ch * 8)
                      : (arr == 1) ? (const char*)(g_Kl + kvo + (size_t)row * HH + ch * 8)
                                   : (const char*)(g_V16 + kvo + (size_t)row * HH + ch * 8);
                    CP_ASYNC16(ob + arr * 9216 + row * 144 + ch * 16, src);
                }
                CP_COMMIT();
            }

            // ---- S = (Qh+Ql)(Kh+Kl)^T, 3 terms (log2-domain) ----
            float S[8][4];
            #pragma unroll
            for (int j = 0; j < 8; ++j)
                #pragma unroll
                for (int q = 0; q < 4; ++q) S[j][q] = 0.0f;

            #pragma unroll
            for (int kk = 0; kk < 4; ++kk) {
                uint32_t Kh[8][2], Kl[8][2];
                #pragma unroll
                for (int n2 = 0; n2 < 4; ++n2) {
                    uint32_t a = sb + (n2 * 16 + li + nh8) * 144 + kk * 32 + kh16;
                    ldsm_x4(&Kh[2 * n2][0], a + A_KH);
                    ldsm_x4(&Kl[2 * n2][0], a + A_KL);
                }
                #pragma unroll
                for (int j = 0; j < 8; ++j) {
                    mma_bf16(S[j], qh[kk], Kh[j]);
                    mma_bf16(S[j], qh[kk], Kl[j]);
                    mma_bf16(S[j], ql[kk], Kh[j]);
                }
            }

            if (kb == qb) {
                const int rA = w * 16 + g, rB = rA + 8;
                #pragma unroll
                for (int j = 0; j < 8; ++j) {
                    const int c0 = j * 8 + t2;
                    if (c0 > rA)     S[j][0] = -1e30f;
                    if (c0 + 1 > rA) S[j][1] = -1e30f;
                    if (c0 > rB)     S[j][2] = -1e30f;
                    if (c0 + 1 > rB) S[j][3] = -1e30f;
                }
            }

            // ---- online softmax, exp2 domain; P emitted as fp16x2 frags ----
            float mx0 = fmaxf(S[0][0], S[0][1]);
            float mx1 = fmaxf(S[0][2], S[0][3]);
            #pragma unroll
            for (int j = 1; j < 8; ++j) {
                mx0 = fmaxf(mx0, fmaxf(S[j][0], S[j][1]));
                mx1 = fmaxf(mx1, fmaxf(S[j][2], S[j][3]));
            }
            mx0 = fmaxf(mx0, __shfl_xor_sync(0xffffffffu, mx0, 1));
            mx0 = fmaxf(mx0, __shfl_xor_sync(0xffffffffu, mx0, 2));
            mx1 = fmaxf(mx1, __shfl_xor_sync(0xffffffffu, mx1, 1));
            mx1 = fmaxf(mx1, __shfl_xor_sync(0xffffffffu, mx1, 2));
            const float mn0 = fmaxf(m_[0], mx0);
            const float mn1 = fmaxf(m_[1], mx1);
            const float corr0 = ex2f(m_[0] - mn0);
            const float corr1 = ex2f(m_[1] - mn1);
            m_[0] = mn0; m_[1] = mn1;

            uint32_t EA[8], EB[8];
            float rs0 = 0.0f, rs1 = 0.0f;
            #pragma unroll
            for (int j = 0; j < 8; ++j) {
                EA[j] = ex2_h2(pack_h2(S[j][0] - mn0, S[j][1] - mn0));
                EB[j] = ex2_h2(pack_h2(S[j][2] - mn1, S[j][3] - mn1));
                float2 fa = __half22float2(*(__half2*)&EA[j]);
                float2 fb = __half22float2(*(__half2*)&EB[j]);
                rs0 += fa.x + fa.y;
                rs1 += fb.x + fb.y;
            }
            rs0 += __shfl_xor_sync(0xffffffffu, rs0, 1);
            rs0 += __shfl_xor_sync(0xffffffffu, rs0, 2);
            rs1 += __shfl_xor_sync(0xffffffffu, rs1, 1);
            rs1 += __shfl_xor_sync(0xffffffffu, rs1, 2);
            l_[0] = l_[0] * corr0 + rs0;
            l_[1] = l_[1] * corr1 + rs1;
            #pragma unroll
            for (int j = 0; j < 8; ++j) {
                O[j][0] *= corr0; O[j][1] *= corr0;
                O[j][2] *= corr1; O[j][3] *= corr1;
            }

            // ---- O += P V, single-term fp16 ----
            #pragma unroll
            for (int kk = 0; kk < 4; ++kk) {
                uint32_t p[4] = {EA[2 * kk], EB[2 * kk], EA[2 * kk + 1], EB[2 * kk + 1]};
                uint32_t Vf[8][2];
                #pragma unroll
                for (int h2 = 0; h2 < 4; ++h2) {
                    uint32_t a = sb + A_V + (kk * 16 + li + sh8) * 144 + h2 * 32 + hh16;
                    ldsm_x4_t(&Vf[2 * h2][0], a);
                }
                #pragma unroll
                for (int j = 0; j < 8; ++j)
                    mma_f16(O[j], p, Vf[j]);
            }

            CP_WAIT0();
            __syncthreads();
        }

        // ---- epilogue ----
        const float iA = 1.0f / l_[0], iB = 1.0f / l_[1];
        const int rowA = qb * 64 + w * 16 + g;
        float* ob = out + (size_t)b * SS * HH;
        #pragma unroll
        for (int j = 0; j < 8; ++j) {
            const int col = j * 8 + t2;
            float2 v0 = {O[j][0] * iA, O[j][1] * iA};
            float2 v1 = {O[j][2] * iB, O[j][3] * iB};
            *(float2*)&ob[(size_t)rowA * HH + col] = v0;
            *(float2*)&ob[(size_t)(rowA + 8) * HH + col] = v1;
        }
        __syncthreads();
    }
}

// ---------------------------------------------------------------------------
extern "C" void kernel_launch(void* const* d_in, const int* in_sizes, int n_in,
                              void* d_out, int out_size)
{
    (void)in_sizes; (void)n_in; (void)out_size;
    const float* x  = (const float*)d_in[0];
    const float* Wq = (const float*)d_in[1];
    const float* Wk = (const float*)d_in[2];
    const float* Wv = (const float*)d_in[3];
    float* out = (float*)d_out;

    static int attr_set = 0;
    const int gemm_smem = 2 * G_STG;                // 147456
    const int attn_smem = A_ST0 + 2 * A_STG;        // 73728
    if (!attr_set) {
        cudaFuncSetAttribute(qkv_mma_kernel,
                             cudaFuncAttributeMaxDynamicSharedMemorySize, gemm_smem);
        cudaFuncSetAttribute(attn_mma_kernel,
                             cudaFuncAttributeMaxDynamicSharedMemorySize, attn_smem);
        attr_set = 1;
    }

    wconv_kernel<<<(NTOT * DD + 255) / 256, 256>>>(Wq, Wk, Wv);
    qkv_mma_kernel<<<SS * BB / 64, 256, gemm_smem>>>(x);
    attn_mma_kernel<<<dim3(32, 4), 128, attn_smem>>>(out);
}

// round 10
// speedup vs baseline: 3.6796x; 1.0504x over previous
#include <cuda_runtime.h>
#include <cuda_bf16.h>
#include <cuda_fp16.h>
#include <cstdint>

#define BB 4
#define SS 4096
#define DD 1024
#define HH 64
#define NTOT 192

// bf16 hi/lo Q,K scratch; V in single fp16 (PV product is single-term fp16).
__device__ __nv_bfloat16 g_Qh[BB * SS * HH];
__device__ __nv_bfloat16 g_Ql[BB * SS * HH];
__device__ __nv_bfloat16 g_Kh[BB * SS * HH];
__device__ __nv_bfloat16 g_Kl[BB * SS * HH];
__device__ __half        g_V16[BB * SS * HH];
// W hi/lo, transposed to [N=192][K=1024]; Wq pre-scaled by 0.125*log2(e)
__device__ __nv_bfloat16 g_wh[NTOT * DD];
__device__ __nv_bfloat16 g_wl[NTOT * DD];

// ---------------------------------------------------------------------------
// Stable-PTX helpers (harness emits compute_103 PTX: no tcgen05 allowed)
// ---------------------------------------------------------------------------
__device__ __forceinline__ uint32_t smem_u32(const void* p) {
    uint32_t a;
    asm("{ .reg .u64 t; cvta.to.shared.u64 t, %1; cvt.u32.u64 %0, t; }" : "=r"(a) : "l"(p));
    return a;
}
__device__ __forceinline__ void mma_bf16(float* c, const uint32_t* a, const uint32_t* b) {
    asm volatile(
        "mma.sync.aligned.m16n8k16.row.col.f32.bf16.bf16.f32 "
        "{%0,%1,%2,%3}, {%4,%5,%6,%7}, {%8,%9}, {%0,%1,%2,%3};"
        : "+f"(c[0]), "+f"(c[1]), "+f"(c[2]), "+f"(c[3])
        : "r"(a[0]), "r"(a[1]), "r"(a[2]), "r"(a[3]), "r"(b[0]), "r"(b[1]));
}
__device__ __forceinline__ void mma_f16(float* c, const uint32_t* a, const uint32_t* b) {
    asm volatile(
        "mma.sync.aligned.m16n8k16.row.col.f32.f16.f16.f32 "
        "{%0,%1,%2,%3}, {%4,%5,%6,%7}, {%8,%9}, {%0,%1,%2,%3};"
        : "+f"(c[0]), "+f"(c[1]), "+f"(c[2]), "+f"(c[3])
        : "r"(a[0]), "r"(a[1]), "r"(a[2]), "r"(a[3]), "r"(b[0]), "r"(b[1]));
}
__device__ __forceinline__ void ldsm_x4(uint32_t* r, uint32_t addr) {
    asm volatile("ldmatrix.sync.aligned.m8n8.x4.shared.b16 {%0,%1,%2,%3}, [%4];"
                 : "=r"(r[0]), "=r"(r[1]), "=r"(r[2]), "=r"(r[3]) : "r"(addr));
}
__device__ __forceinline__ void ldsm_x4_t(uint32_t* r, uint32_t addr) {
    asm volatile("ldmatrix.sync.aligned.m8n8.x4.trans.shared.b16 {%0,%1,%2,%3}, [%4];"
                 : "=r"(r[0]), "=r"(r[1]), "=r"(r[2]), "=r"(r[3]) : "r"(addr));
}
__device__ __forceinline__ uint32_t pack_bf16(float lo, float hi) {
    uint32_t r;
    asm("cvt.rn.bf16x2.f32 %0, %1, %2;" : "=r"(r) : "f"(hi), "f"(lo));
    return r;
}
__device__ __forceinline__ uint32_t pack_h2(float lo, float hi) {   // lo -> low half
    uint32_t r;
    asm("cvt.rn.f16x2.f32 %0, %1, %2;" : "=r"(r) : "f"(hi), "f"(lo));
    return r;
}
__device__ __forceinline__ uint32_t ex2_h2(uint32_t h2) {
    uint32_t r;
    asm("ex2.approx.f16x2 %0, %1;" : "=r"(r) : "r"(h2));
    return r;
}
__device__ __forceinline__ float ex2f(float x) {
    float r;
    asm("ex2.approx.f32 %0, %1;" : "=f"(r) : "f"(x));
    return r;
}
// v = hi + lo bf16 split of a float pair (x -> low half, y -> high half)
__device__ __forceinline__ void split2(float x, float y, uint32_t& hi, uint32_t& lo) {
    hi = pack_bf16(x, y);
    float hx = __uint_as_float(hi << 16);
    float hy = __uint_as_float(hi & 0xffff0000u);
    lo = pack_bf16(x - hx, y - hy);
}
#define CP_ASYNC16(dst, src) \
    asm volatile("cp.async.cg.shared.global [%0], [%1], 16;" :: "r"(dst), "l"(src) : "memory")
#define CP_COMMIT() asm volatile("cp.async.commit_group;" ::: "memory")
#define CP_WAIT0()  asm volatile("cp.async.wait_group 0;" ::: "memory")
#define GBAR(id)    asm volatile("bar.sync %0, 128;" :: "r"(id) : "memory")

// ---------------------------------------------------------------------------
// wconv: W fp32 [1024,64] x3 -> hi/lo bf16 [192,1024].
// Wq scaled by 0.125*log2(e) so attention scores are in log2 domain (exp2 softmax).
// ---------------------------------------------------------------------------
__global__ void wconv_kernel(const float* __restrict__ Wq,
                             const float* __restrict__ Wk,
                             const float* __restrict__ Wv)
{
    int i = blockIdx.x * 256 + threadIdx.x;
    if (i >= NTOT * DD) return;
    int n = i / DD, k = i - n * DD;
    int t = n >> 6, h = n & 63;
    const float* W = (t == 0) ? Wq : ((t == 1) ? Wk : Wv);
    float v = W[(size_t)k * HH + h] * ((t == 0) ? 0.125f * 1.4426950408889634f : 1.0f);
    __nv_bfloat16 hi = __float2bfloat16(v);
    g_wh[i] = hi;
    g_wl[i] = __float2bfloat16(v - __bfloat162float(hi));
}

// ---------------------------------------------------------------------------
// QKV GEMM (unchanged): C[16384,192] = x * W^T via split-bf16 HMMA (3 terms).
// ---------------------------------------------------------------------------
#define G_STG   73728
#define G_AH    0
#define G_AL    9216
#define G_BH    18432
#define G_BL    46080

__global__ __launch_bounds__(256, 1) void qkv_mma_kernel(const float* __restrict__ x)
{
    extern __shared__ char smem[];
    const uint32_t sm0 = smem_u32(smem);
    const int tid = threadIdx.x;
    const int wid = tid >> 5, lane = tid & 31;
    const int wm = wid & 1, wn = wid >> 1;
    const int m0 = blockIdx.x * 64;

    const int li  = lane & 7;
    const int r16 = lane & 15;
    const int hfA = (lane >> 4) * 16;
    const int nh8 = ((lane >> 4) & 1) * 8;
    const int kh16 = ((lane >> 3) & 1) * 16;

    float acc[2][6][4];
    #pragma unroll
    for (int mi = 0; mi < 2; ++mi)
        #pragma unroll
        for (int j = 0; j < 6; ++j)
            #pragma unroll
            for (int q = 0; q < 4; ++q) acc[mi][j][q] = 0.0f;

    const int ar  = tid >> 2;
    const int ac0 = (tid & 3) * 16;

    float4 av[4];
    {
        const float* ap = x + (size_t)(m0 + ar) * DD + ac0;
        #pragma unroll
        for (int i = 0; i < 4; ++i) av[i] = *(const float4*)(ap + 4 * i);
        #pragma unroll
        for (int i = 0; i < 6; ++i) {
            int id = tid + 256 * i, row = id >> 3, ch = id & 7;
            CP_ASYNC16(sm0 + G_BH + row * 144 + ch * 16, g_wh + (size_t)row * DD + ch * 8);
            CP_ASYNC16(sm0 + G_BL + row * 144 + ch * 16, g_wl + (size_t)row * DD + ch * 8);
        }
        CP_COMMIT();
        char* st = smem;
        #pragma unroll
        for (int i = 0; i < 4; ++i) {
            uint32_t h0, l0, h1, l1;
            split2(av[i].x, av[i].y, h0, l0);
            split2(av[i].z, av[i].w, h1, l1);
            uint2 hv = {h0, h1}, lv = {l0, l1};
            *(uint2*)(st + G_AH + ar * 144 + ac0 * 2 + i * 8) = hv;
            *(uint2*)(st + G_AL + ar * 144 + ac0 * 2 + i * 8) = lv;
        }
        CP_WAIT0();
        __syncthreads();
    }

    for (int c = 0; c < 16; ++c) {
        const int s = c & 1;
        const uint32_t sb = sm0 + s * G_STG;

        if (c < 15) {
            const float* ap = x + (size_t)(m0 + ar) * DD + (c + 1) * 64 + ac0;
            #pragma unroll
            for (int i = 0; i < 4; ++i) av[i] = *(const float4*)(ap + 4 * i);
            const uint32_t ob = sm0 + (s ^ 1) * G_STG;
            #pragma unroll
            for (int i = 0; i < 6; ++i) {
                int id = tid + 256 * i, row = id >> 3, ch = id & 7;
                CP_ASYNC16(ob + G_BH + row * 144 + ch * 16,
                           g_wh + (size_t)row * DD + (c + 1) * 64 + ch * 8);
                CP_ASYNC16(ob + G_BL + row * 144 + ch * 16,
                           g_wl + (size_t)row * DD + (c + 1) * 64 + ch * 8);
            }
            CP_COMMIT();
        }

        #pragma unroll
        for (int kk = 0; kk < 4; ++kk) {
            uint32_t Ah[2][4], Al[2][4];
            #pragma unroll
            for (int mi = 0; mi < 2; ++mi) {
                uint32_t a = sb + (wm * 32 + mi * 16 + r16) * 144 + kk * 32 + hfA;
                ldsm_x4(Ah[mi], a + G_AH);
                ldsm_x4(Al[mi], a + G_AL);
            }
            uint32_t Bh[6][2], Bl[6][2];
            #pragma unroll
            for (int j2 = 0; j2 < 3; ++j2) {
                uint32_t a = sb + (wn * 48 + j2 * 16 + li + nh8) * 144 + kk * 32 + kh16;
                ldsm_x4(&Bh[2 * j2][0], a + G_BH);
                ldsm_x4(&Bl[2 * j2][0], a + G_BL);
            }
            #pragma unroll
            for (int mi = 0; mi < 2; ++mi)
                #pragma unroll
                for (int j = 0; j < 6; ++j) {
                    mma_bf16(acc[mi][j], Ah[mi], Bh[j]);
                    mma_bf16(acc[mi][j], Ah[mi], Bl[j]);
                    mma_bf16(acc[mi][j], Al[mi], Bh[j]);
                }
        }

        if (c < 15) {
            char* st = smem + (s ^ 1) * G_STG;
            #pragma unroll
            for (int i = 0; i < 4; ++i) {
                uint32_t h0, l0, h1, l1;
                split2(av[i].x, av[i].y, h0, l0);
                split2(av[i].z, av[i].w, h1, l1);
                uint2 hv = {h0, h1}, lv = {l0, l1};
                *(uint2*)(st + G_AH + ar * 144 + ac0 * 2 + i * 8) = hv;
                *(uint2*)(st + G_AL + ar * 144 + ac0 * 2 + i * 8) = lv;
            }
        }
        CP_WAIT0();
        __syncthreads();
    }

    const int g = lane >> 2, t2 = (lane & 3) * 2;
    #pragma unroll
    for (int mi = 0; mi < 2; ++mi) {
        #pragma unroll
        for (int j = 0; j < 6; ++j) {
            const int nG = wn * 48 + j * 8 + t2;
            const int tns = nG >> 6, h = nG & 63;
            const int rowA = m0 + wm * 32 + mi * 16 + g;
            if (tns == 2) {
                *(uint32_t*)&g_V16[(size_t)rowA * HH + h] =
                    pack_h2(acc[mi][j][0], acc[mi][j][1]);
                *(uint32_t*)&g_V16[(size_t)(rowA + 8) * HH + h] =
                    pack_h2(acc[mi][j][2], acc[mi][j][3]);
            } else {
                __nv_bfloat16* hp = (tns == 0) ? g_Qh : g_Kh;
                __nv_bfloat16* lp = (tns == 0) ? g_Ql : g_Kl;
                uint32_t hi, lo;
                split2(acc[mi][j][0], acc[mi][j][1], hi, lo);
                *(uint32_t*)&hp[(size_t)rowA * HH + h] = hi;
                *(uint32_t*)&lp[(size_t)rowA * HH + h] = lo;
                split2(acc[mi][j][2], acc[mi][j][3], hi, lo);
                *(uint32_t*)&hp[(size_t)(rowA + 8) * HH + h] = hi;
                *(uint32_t*)&lp[(size_t)(rowA + 8) * HH + h] = lo;
            }
        }
    }
}

// ---------------------------------------------------------------------------
// Attention: causal flash, split-KV across two 4-warp groups (256 threads).
// grid (32,4): CTA handles q-blocks {p, 63-p}. Group g processes kb ≡ g (mod 2)
// with its own double-buffered stages + named barrier; partial (m,l,O) merged
// via smem LSE merge at pass end. QK = 3-term bf16; PV = 1-term fp16.
// ---------------------------------------------------------------------------
#define A_QH 0
#define A_QL 9216
#define A_ST0 18432      // 4 stages (2 per group); per stage: Kh | Kl | V(fp16)
#define A_STG 27648
#define A_KH 0
#define A_KL 9216
#define A_V  18432
#define A_SMEM (A_ST0 + 4 * A_STG)    // 129024

__global__ __launch_bounds__(256, 1) void attn_mma_kernel(float* __restrict__ out)
{
    extern __shared__ char smem[];
    const uint32_t sm0 = smem_u32(smem);
    const int b = blockIdx.y, pid = blockIdx.x;
    const int tid = threadIdx.x;
    const int w = tid >> 5, lane = tid & 31;
    const int grp = w >> 2, wg = w & 3;      // group 0/1, warp-in-group 0..3
    const int gtid = tid & 127;              // thread id within group

    const int li   = lane & 7;
    const int r16  = lane & 15;
    const int hfA  = (lane >> 4) * 16;
    const int nh8  = ((lane >> 4) & 1) * 8;
    const int kh16 = ((lane >> 3) & 1) * 16;
    const int sh8  = ((lane >> 3) & 1) * 8;
    const int hh16 = ((lane >> 4) & 1) * 16;
    const int g = lane >> 2, t2 = (lane & 3) * 2;

    const size_t base = (size_t)b * SS * HH;

    for (int pass = 0; pass < 2; ++pass) {
        const int qb = pass ? (63 - pid) : pid;
        // number of tiles for this group: kb = grp, grp+2, ... <= qb
        const int ng = (qb >= grp) ? (((qb - grp) >> 1) + 1) : 0;

        // prefetch this group's first tile (kb = grp) into its stage 0
        if (ng > 0) {
            const uint32_t ob = sm0 + A_ST0 + (2 * grp) * A_STG;
            const size_t kvo = base + (size_t)grp * 64 * HH;
            #pragma unroll
            for (int i = 0; i < 12; ++i) {
                int id = gtid + 128 * i;
                int arr = id >> 9, rem = id & 511, row = rem >> 3, ch = rem & 7;
                const char* src =
                    (arr == 0) ? (const char*)(g_Kh + kvo + (size_t)row * HH + ch * 8)
                  : (arr == 1) ? (const char*)(g_Kl + kvo + (size_t)row * HH + ch * 8)
                               : (const char*)(g_V16 + kvo + (size_t)row * HH + ch * 8);
                CP_ASYNC16(ob + arr * 9216 + row * 144 + ch * 16, src);
            }
        }
        CP_COMMIT();
        // load Q tile hi/lo (all 256 threads)
        {
            const size_t qo = base + (size_t)qb * 64 * HH;
            #pragma unroll
            for (int i = 0; i < 4; ++i) {
                int id = tid + 256 * i;
                int arr = id >> 9, rem = id & 511, row = rem >> 3, ch = rem & 7;
                const __nv_bfloat16* src = arr ? g_Ql : g_Qh;
                *(uint4*)(smem + arr * 9216 + row * 144 + ch * 16) =
                    *(const uint4*)(src + qo + (size_t)row * HH + ch * 8);
            }
        }
        CP_WAIT0();
        __syncthreads();

        uint32_t qh[4][4], ql[4][4];
        #pragma unroll
        for (int kk = 0; kk < 4; ++kk) {
            uint32_t a = sm0 + (wg * 16 + r16) * 144 + kk * 32 + hfA;
            ldsm_x4(qh[kk], a + A_QH);
            ldsm_x4(ql[kk], a + A_QL);
        }

        float O[8][4];
        float m_[2] = {-1e30f, -1e30f}, l_[2] = {0.0f, 0.0f};
        #pragma unroll
        for (int j = 0; j < 8; ++j)
            #pragma unroll
            for (int q = 0; q < 4; ++q) O[j][q] = 0.0f;

        for (int t = 0; t < ng; ++t) {
            const int kb = grp + 2 * t;
            const int s = t & 1;
            const uint32_t sb = sm0 + A_ST0 + (2 * grp + s) * A_STG;

            if (t + 1 < ng) {     // prefetch this group's next tile (kb+2)
                const uint32_t ob = sm0 + A_ST0 + (2 * grp + (s ^ 1)) * A_STG;
                const size_t kvo = base + (size_t)(kb + 2) * 64 * HH;
                #pragma unroll
                for (int i = 0; i < 12; ++i) {
                    int id = gtid + 128 * i;
                    int arr = id >> 9, rem = id & 511, row = rem >> 3, ch = rem & 7;
                    const char* src =
                        (arr == 0) ? (const char*)(g_Kh + kvo + (size_t)row * HH + ch * 8)
                      : (arr == 1) ? (const char*)(g_Kl + kvo + (size_t)row * HH + ch * 8)
                                   : (const char*)(g_V16 + kvo + (size_t)row * HH + ch * 8);
                    CP_ASYNC16(ob + arr * 9216 + row * 144 + ch * 16, src);
                }
                CP_COMMIT();
            }

            // ---- S = (Qh+Ql)(Kh+Kl)^T, 3 terms (log2-domain) ----
            float S[8][4];
            #pragma unroll
            for (int j = 0; j < 8; ++j)
                #pragma unroll
                for (int q = 0; q < 4; ++q) S[j][q] = 0.0f;

            #pragma unroll
            for (int kk = 0; kk < 4; ++kk) {
                uint32_t Kh[8][2], Kl[8][2];
                #pragma unroll
                for (int n2 = 0; n2 < 4; ++n2) {
                    uint32_t a = sb + (n2 * 16 + li + nh8) * 144 + kk * 32 + kh16;
                    ldsm_x4(&Kh[2 * n2][0], a + A_KH);
                    ldsm_x4(&Kl[2 * n2][0], a + A_KL);
                }
                #pragma unroll
                for (int j = 0; j < 8; ++j) {
                    mma_bf16(S[j], qh[kk], Kh[j]);
                    mma_bf16(S[j], qh[kk], Kl[j]);
                    mma_bf16(S[j], ql[kk], Kh[j]);
                }
            }

            if (kb == qb) {       // diagonal tile: causal mask (local coords)
                const int rA = wg * 16 + g, rB = rA + 8;
                #pragma unroll
                for (int j = 0; j < 8; ++j) {
                    const int c0 = j * 8 + t2;
                    if (c0 > rA)     S[j][0] = -1e30f;
                    if (c0 + 1 > rA) S[j][1] = -1e30f;
                    if (c0 > rB)     S[j][2] = -1e30f;
                    if (c0 + 1 > rB) S[j][3] = -1e30f;
                }
            }

            // ---- online softmax, exp2 domain; P emitted as fp16x2 frags ----
            float mx0 = fmaxf(S[0][0], S[0][1]);
            float mx1 = fmaxf(S[0][2], S[0][3]);
            #pragma unroll
            for (int j = 1; j < 8; ++j) {
                mx0 = fmaxf(mx0, fmaxf(S[j][0], S[j][1]));
                mx1 = fmaxf(mx1, fmaxf(S[j][2], S[j][3]));
            }
            mx0 = fmaxf(mx0, __shfl_xor_sync(0xffffffffu, mx0, 1));
            mx0 = fmaxf(mx0, __shfl_xor_sync(0xffffffffu, mx0, 2));
            mx1 = fmaxf(mx1, __shfl_xor_sync(0xffffffffu, mx1, 1));
            mx1 = fmaxf(mx1, __shfl_xor_sync(0xffffffffu, mx1, 2));
            const float mn0 = fmaxf(m_[0], mx0);
            const float mn1 = fmaxf(m_[1], mx1);
            const float corr0 = ex2f(m_[0] - mn0);
            const float corr1 = ex2f(m_[1] - mn1);
            m_[0] = mn0; m_[1] = mn1;

            uint32_t EA[8], EB[8];
            float rs0 = 0.0f, rs1 = 0.0f;
            #pragma unroll
            for (int j = 0; j < 8; ++j) {
                EA[j] = ex2_h2(pack_h2(S[j][0] - mn0, S[j][1] - mn0));
                EB[j] = ex2_h2(pack_h2(S[j][2] - mn1, S[j][3] - mn1));
                float2 fa = __half22float2(*(__half2*)&EA[j]);
                float2 fb = __half22float2(*(__half2*)&EB[j]);
                rs0 += fa.x + fa.y;
                rs1 += fb.x + fb.y;
            }
            rs0 += __shfl_xor_sync(0xffffffffu, rs0, 1);
            rs0 += __shfl_xor_sync(0xffffffffu, rs0, 2);
            rs1 += __shfl_xor_sync(0xffffffffu, rs1, 1);
            rs1 += __shfl_xor_sync(0xffffffffu, rs1, 2);
            l_[0] = l_[0] * corr0 + rs0;
            l_[1] = l_[1] * corr1 + rs1;
            #pragma unroll
            for (int j = 0; j < 8; ++j) {
                O[j][0] *= corr0; O[j][1] *= corr0;
                O[j][2] *= corr1; O[j][3] *= corr1;
            }

            // ---- O += P V, single-term fp16 ----
            #pragma unroll
            for (int kk = 0; kk < 4; ++kk) {
                uint32_t p[4] = {EA[2 * kk], EB[2 * kk], EA[2 * kk + 1], EB[2 * kk + 1]};
                uint32_t Vf[8][2];
                #pragma unroll
                for (int h2 = 0; h2 < 4; ++h2) {
                    uint32_t a = sb + A_V + (kk * 16 + li + sh8) * 144 + h2 * 32 + hh16;
                    ldsm_x4_t(&Vf[2 * h2][0], a);
                }
                #pragma unroll
                for (int j = 0; j < 8; ++j)
                    mma_f16(O[j], p, Vf[j]);
            }

            CP_WAIT0();
            GBAR(1 + grp);       // group-local barrier (stages are per-group)
        }

        // ---- merge partials: group1 -> smem, group0 combines + writes ----
        __syncthreads();         // all tiles done; stage smem reusable
        float* mb = (float*)(smem + A_ST0);
        if (grp == 1) {
            float* slot = mb + gtid * 36;
            #pragma unroll
            for (int j = 0; j < 8; ++j)
                #pragma unroll
                for (int q = 0; q < 4; ++q) slot[j * 4 + q] = O[j][q];
            slot[32] = m_[0]; slot[33] = m_[1];
            slot[34] = l_[0]; slot[35] = l_[1];
        }
        __syncthreads();
        if (grp == 0) {
            const float* slot = mb + gtid * 36;
            const float m1a = slot[32], m1b = slot[33];
            const float l1a = slot[34], l1b = slot[35];
            const float mnA = fmaxf(m_[0], m1a), mnB = fmaxf(m_[1], m1b);
            const float c00 = ex2f(m_[0] - mnA), c01 = ex2f(m1a - mnA);
            const float c10 = ex2f(m_[1] - mnB), c11 = ex2f(m1b - mnB);
            const float iA = 1.0f / (l_[0] * c00 + l1a * c01);
            const float iB = 1.0f / (l_[1] * c10 + l1b * c11);
            const int rowA = qb * 64 + wg * 16 + g;
            float* ob = out + (size_t)b * SS * HH;
            #pragma unroll
            for (int j = 0; j < 8; ++j) {
                const int col = j * 8 + t2;
                float2 v0, v1;
                v0.x = (O[j][0] * c00 + slot[j * 4 + 0] * c01) * iA;
                v0.y = (O[j][1] * c00 + slot[j * 4 + 1] * c01) * iA;
                v1.x = (O[j][2] * c10 + slot[j * 4 + 2] * c11) * iB;
                v1.y = (O[j][3] * c10 + slot[j * 4 + 3] * c11) * iB;
                *(float2*)&ob[(size_t)rowA * HH + col] = v0;
                *(float2*)&ob[(size_t)(rowA + 8) * HH + col] = v1;
            }
        }
        __syncthreads();         // before next pass overwrites Q smem / stages
    }
}

// ---------------------------------------------------------------------------
extern "C" void kernel_launch(void* const* d_in, const int* in_sizes, int n_in,
                              void* d_out, int out_size)
{
    (void)in_sizes; (void)n_in; (void)out_size;
    const float* x  = (const float*)d_in[0];
    const float* Wq = (const float*)d_in[1];
    const float* Wk = (const float*)d_in[2];
    const float* Wv = (const float*)d_in[3];
    float* out = (float*)d_out;

    static int attr_set = 0;
    const int gemm_smem = 2 * G_STG;                // 147456
    const int attn_smem = A_SMEM;                   // 129024
    if (!attr_set) {
        cudaFuncSetAttribute(qkv_mma_kernel,
                             cudaFuncAttributeMaxDynamicSharedMemorySize, gemm_smem);
        cudaFuncSetAttribute(attn_mma_kernel,
                             cudaFuncAttributeMaxDynamicSharedMemorySize, attn_smem);
        attr_set = 1;
    }

    wconv_kernel<<<(NTOT * DD + 255) / 256, 256>>>(Wq, Wk, Wv);
    qkv_mma_kernel<<<SS * BB / 64, 256, gemm_smem>>>(x);
    attn_mma_kernel<<<dim3(32, 4), 256, attn_smem>>>(out);
}

// round 11
// speedup vs baseline: 3.8687x; 1.0514x over previous
#include <cuda_runtime.h>
#include <cuda_bf16.h>
#include <cuda_fp16.h>
#include <cstdint>

#define BB 4
#define SS 4096
#define DD 1024
#define HH 64
#define NTOT 192

// Attention operands: Q single fp16 (carries 0.125*log2e), K fp16 hi/lo, V fp16.
__device__ __half g_Q16[BB * SS * HH];
__device__ __half g_K16h[BB * SS * HH];
__device__ __half g_K16l[BB * SS * HH];
__device__ __half g_V16[BB * SS * HH];
// W hi/lo bf16, transposed to [N=192][K=1024]; Wq pre-scaled by 0.125*log2(e)
__device__ __nv_bfloat16 g_wh[NTOT * DD];
__device__ __nv_bfloat16 g_wl[NTOT * DD];

// ---------------------------------------------------------------------------
// Stable-PTX helpers (harness emits compute_103 PTX: no tcgen05 allowed)
// ---------------------------------------------------------------------------
__device__ __forceinline__ uint32_t smem_u32(const void* p) {
    uint32_t a;
    asm("{ .reg .u64 t; cvta.to.shared.u64 t, %1; cvt.u32.u64 %0, t; }" : "=r"(a) : "l"(p));
    return a;
}
__device__ __forceinline__ void mma_bf16(float* c, const uint32_t* a, const uint32_t* b) {
    asm volatile(
        "mma.sync.aligned.m16n8k16.row.col.f32.bf16.bf16.f32 "
        "{%0,%1,%2,%3}, {%4,%5,%6,%7}, {%8,%9}, {%0,%1,%2,%3};"
        : "+f"(c[0]), "+f"(c[1]), "+f"(c[2]), "+f"(c[3])
        : "r"(a[0]), "r"(a[1]), "r"(a[2]), "r"(a[3]), "r"(b[0]), "r"(b[1]));
}
__device__ __forceinline__ void mma_f16(float* c, const uint32_t* a, const uint32_t* b) {
    asm volatile(
        "mma.sync.aligned.m16n8k16.row.col.f32.f16.f16.f32 "
        "{%0,%1,%2,%3}, {%4,%5,%6,%7}, {%8,%9}, {%0,%1,%2,%3};"
        : "+f"(c[0]), "+f"(c[1]), "+f"(c[2]), "+f"(c[3])
        : "r"(a[0]), "r"(a[1]), "r"(a[2]), "r"(a[3]), "r"(b[0]), "r"(b[1]));
}
__device__ __forceinline__ void ldsm_x4(uint32_t* r, uint32_t addr) {
    asm volatile("ldmatrix.sync.aligned.m8n8.x4.shared.b16 {%0,%1,%2,%3}, [%4];"
                 : "=r"(r[0]), "=r"(r[1]), "=r"(r[2]), "=r"(r[3]) : "r"(addr));
}
__device__ __forceinline__ void ldsm_x4_t(uint32_t* r, uint32_t addr) {
    asm volatile("ldmatrix.sync.aligned.m8n8.x4.trans.shared.b16 {%0,%1,%2,%3}, [%4];"
                 : "=r"(r[0]), "=r"(r[1]), "=r"(r[2]), "=r"(r[3]) : "r"(addr));
}
__device__ __forceinline__ uint32_t pack_bf16(float lo, float hi) {
    uint32_t r;
    asm("cvt.rn.bf16x2.f32 %0, %1, %2;" : "=r"(r) : "f"(hi), "f"(lo));
    return r;
}
__device__ __forceinline__ uint32_t pack_h2(float lo, float hi) {   // lo -> low half
    uint32_t r;
    asm("cvt.rn.f16x2.f32 %0, %1, %2;" : "=r"(r) : "f"(hi), "f"(lo));
    return r;
}
__device__ __forceinline__ uint32_t ex2_h2(uint32_t h2) {
    uint32_t r;
    asm("ex2.approx.f16x2 %0, %1;" : "=r"(r) : "r"(h2));
    return r;
}
__device__ __forceinline__ float ex2f(float x) {
    float r;
    asm("ex2.approx.f32 %0, %1;" : "=f"(r) : "f"(x));
    return r;
}
// v = hi + lo bf16 split of a float pair (x -> low half, y -> high half)
__device__ __forceinline__ void split2(float x, float y, uint32_t& hi, uint32_t& lo) {
    hi = pack_bf16(x, y);
    float hx = __uint_as_float(hi << 16);
    float hy = __uint_as_float(hi & 0xffff0000u);
    lo = pack_bf16(x - hx, y - hy);
}
// v = hi + lo fp16 split of a float pair
__device__ __forceinline__ void split2h(float x, float y, uint32_t& hi, uint32_t& lo) {
    hi = pack_h2(x, y);
    float2 f = __half22float2(*(__half2*)&hi);
    lo = pack_h2(x - f.x, y - f.y);
}
#define CP_ASYNC16(dst, src) \
    asm volatile("cp.async.cg.shared.global [%0], [%1], 16;" :: "r"(dst), "l"(src) : "memory")
#define CP_COMMIT() asm volatile("cp.async.commit_group;" ::: "memory")
#define CP_WAIT0()  asm volatile("cp.async.wait_group 0;" ::: "memory")
#define GBAR(id)    asm volatile("bar.sync %0, 128;" :: "r"(id) : "memory")

// ---------------------------------------------------------------------------
// wconv: W fp32 [1024,64] x3 -> hi/lo bf16 [192,1024].
// Wq scaled by 0.125*log2(e) so attention scores are in log2 domain (exp2 softmax).
// ---------------------------------------------------------------------------
__global__ void wconv_kernel(const float* __restrict__ Wq,
                             const float* __restrict__ Wk,
                             const float* __restrict__ Wv)
{
    int i = blockIdx.x * 256 + threadIdx.x;
    if (i >= NTOT * DD) return;
    int n = i / DD, k = i - n * DD;
    int t = n >> 6, h = n & 63;
    const float* W = (t == 0) ? Wq : ((t == 1) ? Wk : Wv);
    float v = W[(size_t)k * HH + h] * ((t == 0) ? 0.125f * 1.4426950408889634f : 1.0f);
    __nv_bfloat16 hi = __float2bfloat16(v);
    g_wh[i] = hi;
    g_wl[i] = __float2bfloat16(v - __bfloat162float(hi));
}

// ---------------------------------------------------------------------------
// QKV GEMM: C[16384,192] = x * W^T via split-bf16 HMMA (3 terms).
// Epilogue: Q -> fp16 single; K -> fp16 hi/lo; V -> fp16.
// ---------------------------------------------------------------------------
#define G_STG   73728
#define G_AH    0
#define G_AL    9216
#define G_BH    18432
#define G_BL    46080

__global__ __launch_bounds__(256, 1) void qkv_mma_kernel(const float* __restrict__ x)
{
    extern __shared__ char smem[];
    const uint32_t sm0 = smem_u32(smem);
    const int tid = threadIdx.x;
    const int wid = tid >> 5, lane = tid & 31;
    const int wm = wid & 1, wn = wid >> 1;
    const int m0 = blockIdx.x * 64;

    const int li  = lane & 7;
    const int r16 = lane & 15;
    const int hfA = (lane >> 4) * 16;
    const int nh8 = ((lane >> 4) & 1) * 8;
    const int kh16 = ((lane >> 3) & 1) * 16;

    float acc[2][6][4];
    #pragma unroll
    for (int mi = 0; mi < 2; ++mi)
        #pragma unroll
        for (int j = 0; j < 6; ++j)
            #pragma unroll
            for (int q = 0; q < 4; ++q) acc[mi][j][q] = 0.0f;

    const int ar  = tid >> 2;
    const int ac0 = (tid & 3) * 16;

    float4 av[4];
    {
        const float* ap = x + (size_t)(m0 + ar) * DD + ac0;
        #pragma unroll
        for (int i = 0; i < 4; ++i) av[i] = *(const float4*)(ap + 4 * i);
        #pragma unroll
        for (int i = 0; i < 6; ++i) {
            int id = tid + 256 * i, row = id >> 3, ch = id & 7;
            CP_ASYNC16(sm0 + G_BH + row * 144 + ch * 16, g_wh + (size_t)row * DD + ch * 8);
            CP_ASYNC16(sm0 + G_BL + row * 144 + ch * 16, g_wl + (size_t)row * DD + ch * 8);
        }
        CP_COMMIT();
        char* st = smem;
        #pragma unroll
        for (int i = 0; i < 4; ++i) {
            uint32_t h0, l0, h1, l1;
            split2(av[i].x, av[i].y, h0, l0);
            split2(av[i].z, av[i].w, h1, l1);
            uint2 hv = {h0, h1}, lv = {l0, l1};
            *(uint2*)(st + G_AH + ar * 144 + ac0 * 2 + i * 8) = hv;
            *(uint2*)(st + G_AL + ar * 144 + ac0 * 2 + i * 8) = lv;
        }
        CP_WAIT0();
        __syncthreads();
    }

    for (int c = 0; c < 16; ++c) {
        const int s = c & 1;
        const uint32_t sb = sm0 + s * G_STG;

        if (c < 15) {
            const float* ap = x + (size_t)(m0 + ar) * DD + (c + 1) * 64 + ac0;
            #pragma unroll
            for (int i = 0; i < 4; ++i) av[i] = *(const float4*)(ap + 4 * i);
            const uint32_t ob = sm0 + (s ^ 1) * G_STG;
            #pragma unroll
            for (int i = 0; i < 6; ++i) {
                int id = tid + 256 * i, row = id >> 3, ch = id & 7;
                CP_ASYNC16(ob + G_BH + row * 144 + ch * 16,
                           g_wh + (size_t)row * DD + (c + 1) * 64 + ch * 8);
                CP_ASYNC16(ob + G_BL + row * 144 + ch * 16,
                           g_wl + (size_t)row * DD + (c + 1) * 64 + ch * 8);
            }
            CP_COMMIT();
        }

        #pragma unroll
        for (int kk = 0; kk < 4; ++kk) {
            uint32_t Ah[2][4], Al[2][4];
            #pragma unroll
            for (int mi = 0; mi < 2; ++mi) {
                uint32_t a = sb + (wm * 32 + mi * 16 + r16) * 144 + kk * 32 + hfA;
                ldsm_x4(Ah[mi], a + G_AH);
                ldsm_x4(Al[mi], a + G_AL);
            }
            uint32_t Bh[6][2], Bl[6][2];
            #pragma unroll
            for (int j2 = 0; j2 < 3; ++j2) {
                uint32_t a = sb + (wn * 48 + j2 * 16 + li + nh8) * 144 + kk * 32 + kh16;
                ldsm_x4(&Bh[2 * j2][0], a + G_BH);
                ldsm_x4(&Bl[2 * j2][0], a + G_BL);
            }
            #pragma unroll
            for (int mi = 0; mi < 2; ++mi)
                #pragma unroll
                for (int j = 0; j < 6; ++j) {
                    mma_bf16(acc[mi][j], Ah[mi], Bh[j]);
                    mma_bf16(acc[mi][j], Ah[mi], Bl[j]);
                    mma_bf16(acc[mi][j], Al[mi], Bh[j]);
                }
        }

        if (c < 15) {
            char* st = smem + (s ^ 1) * G_STG;
            #pragma unroll
            for (int i = 0; i < 4; ++i) {
                uint32_t h0, l0, h1, l1;
                split2(av[i].x, av[i].y, h0, l0);
                split2(av[i].z, av[i].w, h1, l1);
                uint2 hv = {h0, h1}, lv = {l0, l1};
                *(uint2*)(st + G_AH + ar * 144 + ac0 * 2 + i * 8) = hv;
                *(uint2*)(st + G_AL + ar * 144 + ac0 * 2 + i * 8) = lv;
            }
        }
        CP_WAIT0();
        __syncthreads();
    }

    // ---- epilogue: Q -> fp16; K -> fp16 hi/lo; V -> fp16 ----
    const int g = lane >> 2, t2 = (lane & 3) * 2;
    #pragma unroll
    for (int mi = 0; mi < 2; ++mi) {
        #pragma unroll
        for (int j = 0; j < 6; ++j) {
            const int nG = wn * 48 + j * 8 + t2;
            const int tns = nG >> 6, h = nG & 63;
            const int rowA = m0 + wm * 32 + mi * 16 + g;
            if (tns == 0) {
                *(uint32_t*)&g_Q16[(size_t)rowA * HH + h] =
                    pack_h2(acc[mi][j][0], acc[mi][j][1]);
                *(uint32_t*)&g_Q16[(size_t)(rowA + 8) * HH + h] =
                    pack_h2(acc[mi][j][2], acc[mi][j][3]);
            } else if (tns == 2) {
                *(uint32_t*)&g_V16[(size_t)rowA * HH + h] =
                    pack_h2(acc[mi][j][0], acc[mi][j][1]);
                *(uint32_t*)&g_V16[(size_t)(rowA + 8) * HH + h] =
                    pack_h2(acc[mi][j][2], acc[mi][j][3]);
            } else {
                uint32_t hi, lo;
                split2h(acc[mi][j][0], acc[mi][j][1], hi, lo);
                *(uint32_t*)&g_K16h[(size_t)rowA * HH + h] = hi;
                *(uint32_t*)&g_K16l[(size_t)rowA * HH + h] = lo;
                split2h(acc[mi][j][2], acc[mi][j][3], hi, lo);
                *(uint32_t*)&g_K16h[(size_t)(rowA + 8) * HH + h] = hi;
                *(uint32_t*)&g_K16l[(size_t)(rowA + 8) * HH + h] = lo;
            }
        }
    }
}

// ---------------------------------------------------------------------------
// Attention: causal flash, split-KV across two 4-warp groups (256 threads).
// QK = 2-term fp16 (q16 x (Kh+Kl)); softmax via ex2.f16x2; PV = 1-term fp16.
// grid (32,4): CTA handles q-blocks {p, 63-p}; group g does kb ≡ g (mod 2).
// ---------------------------------------------------------------------------
#define A_Q   0
#define A_ST0 9216       // 4 stages (2 per group); per stage: Kh | Kl | V (fp16)
#define A_STG 27648
#define A_KH 0
#define A_KL 9216
#define A_V  18432
#define A_SMEM (A_ST0 + 4 * A_STG)    // 119808

__global__ __launch_bounds__(256, 1) void attn_mma_kernel(float* __restrict__ out)
{
    extern __shared__ char smem[];
    const uint32_t sm0 = smem_u32(smem);
    const int b = blockIdx.y, pid = blockIdx.x;
    const int tid = threadIdx.x;
    const int w = tid >> 5, lane = tid & 31;
    const int grp = w >> 2, wg = w & 3;      // group 0/1, warp-in-group 0..3
    const int gtid = tid & 127;              // thread id within group

    const int li   = lane & 7;
    const int r16  = lane & 15;
    const int hfA  = (lane >> 4) * 16;
    const int nh8  = ((lane >> 4) & 1) * 8;
    const int kh16 = ((lane >> 3) & 1) * 16;
    const int sh8  = ((lane >> 3) & 1) * 8;
    const int hh16 = ((lane >> 4) & 1) * 16;
    const int g = lane >> 2, t2 = (lane & 3) * 2;

    const size_t base = (size_t)b * SS * HH;

    for (int pass = 0; pass < 2; ++pass) {
        const int qb = pass ? (63 - pid) : pid;
        const int ng = (qb >= grp) ? (((qb - grp) >> 1) + 1) : 0;

        // prefetch this group's first tile (kb = grp) into its stage 0
        if (ng > 0) {
            const uint32_t ob = sm0 + A_ST0 + (2 * grp) * A_STG;
            const size_t kvo = base + (size_t)grp * 64 * HH;
            #pragma unroll
            for (int i = 0; i < 12; ++i) {
                int id = gtid + 128 * i;
                int arr = id >> 9, rem = id & 511, row = rem >> 3, ch = rem & 7;
                const __half* src = (arr == 0) ? g_K16h : (arr == 1) ? g_K16l : g_V16;
                CP_ASYNC16(ob + arr * 9216 + row * 144 + ch * 16,
                           src + kvo + (size_t)row * HH + ch * 8);
            }
        }
        CP_COMMIT();
        // load Q tile fp16 (all 256 threads; 512 chunks)
        {
            const size_t qo = base + (size_t)qb * 64 * HH;
            #pragma unroll
            for (int i = 0; i < 2; ++i) {
                int id = tid + 256 * i;
                int row = id >> 3, ch = id & 7;
                *(uint4*)(smem + A_Q + row * 144 + ch * 16) =
                    *(const uint4*)(g_Q16 + qo + (size_t)row * HH + ch * 8);
            }
        }
        CP_WAIT0();
        __syncthreads();

        uint32_t q16[4][4];
        #pragma unroll
        for (int kk = 0; kk < 4; ++kk) {
            uint32_t a = sm0 + A_Q + (wg * 16 + r16) * 144 + kk * 32 + hfA;
            ldsm_x4(q16[kk], a);
        }

        float O[8][4];
        float m_[2] = {-1e30f, -1e30f}, l_[2] = {0.0f, 0.0f};
        #pragma unroll
        for (int j = 0; j < 8; ++j)
            #pragma unroll
            for (int q = 0; q < 4; ++q) O[j][q] = 0.0f;

        for (int t = 0; t < ng; ++t) {
            const int kb = grp + 2 * t;
            const int s = t & 1;
            const uint32_t sb = sm0 + A_ST0 + (2 * grp + s) * A_STG;

            if (t + 1 < ng) {     // prefetch this group's next tile (kb+2)
                const uint32_t ob = sm0 + A_ST0 + (2 * grp + (s ^ 1)) * A_STG;
                const size_t kvo = base + (size_t)(kb + 2) * 64 * HH;
                #pragma unroll
                for (int i = 0; i < 12; ++i) {
                    int id = gtid + 128 * i;
                    int arr = id >> 9, rem = id & 511, row = rem >> 3, ch = rem & 7;
                    const __half* src = (arr == 0) ? g_K16h : (arr == 1) ? g_K16l : g_V16;
                    CP_ASYNC16(ob + arr * 9216 + row * 144 + ch * 16,
                               src + kvo + (size_t)row * HH + ch * 8);
                }
                CP_COMMIT();
            }

            // ---- S = q16 (Kh + Kl)^T, 2 terms (log2-domain) ----
            float S[8][4];
            #pragma unroll
            for (int j = 0; j < 8; ++j)
                #pragma unroll
                for (int q = 0; q < 4; ++q) S[j][q] = 0.0f;

            #pragma unroll
            for (int kk = 0; kk < 4; ++kk) {
                uint32_t Kh[8][2], Kl[8][2];
                #pragma unroll
                for (int n2 = 0; n2 < 4; ++n2) {
                    uint32_t a = sb + (n2 * 16 + li + nh8) * 144 + kk * 32 + kh16;
                    ldsm_x4(&Kh[2 * n2][0], a + A_KH);
                    ldsm_x4(&Kl[2 * n2][0], a + A_KL);
                }
                #pragma unroll
                for (int j = 0; j < 8; ++j) {
                    mma_f16(S[j], q16[kk], Kh[j]);
                    mma_f16(S[j], q16[kk], Kl[j]);
                }
            }

            if (kb == qb) {       // diagonal tile: causal mask (local coords)
                const int rA = wg * 16 + g, rB = rA + 8;
                #pragma unroll
                for (int j = 0; j < 8; ++j) {
                    const int c0 = j * 8 + t2;
                    if (c0 > rA)     S[j][0] = -1e30f;
                    if (c0 + 1 > rA) S[j][1] = -1e30f;
                    if (c0 > rB)     S[j][2] = -1e30f;
                    if (c0 + 1 > rB) S[j][3] = -1e30f;
                }
            }

            // ---- online softmax, exp2 domain; P emitted as fp16x2 frags ----
            float mx0 = fmaxf(S[0][0], S[0][1]);
            float mx1 = fmaxf(S[0][2], S[0][3]);
            #pragma unroll
            for (int j = 1; j < 8; ++j) {
                mx0 = fmaxf(mx0, fmaxf(S[j][0], S[j][1]));
                mx1 = fmaxf(mx1, fmaxf(S[j][2], S[j][3]));
            }
            mx0 = fmaxf(mx0, __shfl_xor_sync(0xffffffffu, mx0, 1));
            mx0 = fmaxf(mx0, __shfl_xor_sync(0xffffffffu, mx0, 2));
            mx1 = fmaxf(mx1, __shfl_xor_sync(0xffffffffu, mx1, 1));
            mx1 = fmaxf(mx1, __shfl_xor_sync(0xffffffffu, mx1, 2));
            const float mn0 = fmaxf(m_[0], mx0);
            const float mn1 = fmaxf(m_[1], mx1);
            const float corr0 = ex2f(m_[0] - mn0);
            const float corr1 = ex2f(m_[1] - mn1);
            m_[0] = mn0; m_[1] = mn1;

            uint32_t EA[8], EB[8];
            float rs0 = 0.0f, rs1 = 0.0f;
            #pragma unroll
            for (int j = 0; j < 8; ++j) {
                EA[j] = ex2_h2(pack_h2(S[j][0] - mn0, S[j][1] - mn0));
                EB[j] = ex2_h2(pack_h2(S[j][2] - mn1, S[j][3] - mn1));
                float2 fa = __half22float2(*(__half2*)&EA[j]);
                float2 fb = __half22float2(*(__half2*)&EB[j]);
                rs0 += fa.x + fa.y;
                rs1 += fb.x + fb.y;
            }
            rs0 += __shfl_xor_sync(0xffffffffu, rs0, 1);
            rs0 += __shfl_xor_sync(0xffffffffu, rs0, 2);
            rs1 += __shfl_xor_sync(0xffffffffu, rs1, 1);
            rs1 += __shfl_xor_sync(0xffffffffu, rs1, 2);
            l_[0] = l_[0] * corr0 + rs0;
            l_[1] = l_[1] * corr1 + rs1;
            #pragma unroll
            for (int j = 0; j < 8; ++j) {
                O[j][0] *= corr0; O[j][1] *= corr0;
                O[j][2] *= corr1; O[j][3] *= corr1;
            }

            // ---- O += P V, single-term fp16 ----
            #pragma unroll
            for (int kk = 0; kk < 4; ++kk) {
                uint32_t p[4] = {EA[2 * kk], EB[2 * kk], EA[2 * kk + 1], EB[2 * kk + 1]};
                uint32_t Vf[8][2];
                #pragma unroll
                for (int h2 = 0; h2 < 4; ++h2) {
                    uint32_t a = sb + A_V + (kk * 16 + li + sh8) * 144 + h2 * 32 + hh16;
                    ldsm_x4_t(&Vf[2 * h2][0], a);
                }
                #pragma unroll
                for (int j = 0; j < 8; ++j)
                    mma_f16(O[j], p, Vf[j]);
            }

            CP_WAIT0();
            GBAR(1 + grp);       // group-local barrier (stages are per-group)
        }

        // ---- merge partials: group1 -> smem, group0 combines + writes ----
        __syncthreads();         // all tiles done; stage smem reusable
        float* mb = (float*)(smem + A_ST0);
        if (grp == 1) {
            float* slot = mb + gtid * 36;
            #pragma unroll
            for (int j = 0; j < 8; ++j)
                #pragma unroll
                for (int q = 0; q < 4; ++q) slot[j * 4 + q] = O[j][q];
            slot[32] = m_[0]; slot[33] = m_[1];
            slot[34] = l_[0]; slot[35] = l_[1];
        }
        __syncthreads();
        if (grp == 0) {
            const float* slot = mb + gtid * 36;
            const float m1a = slot[32], m1b = slot[33];
            const float l1a = slot[34], l1b = slot[35];
            const float mnA = fmaxf(m_[0], m1a), mnB = fmaxf(m_[1], m1b);
            const float c00 = ex2f(m_[0] - mnA), c01 = ex2f(m1a - mnA);
            const float c10 = ex2f(m_[1] - mnB), c11 = ex2f(m1b - mnB);
            const float iA = 1.0f / (l_[0] * c00 + l1a * c01);
            const float iB = 1.0f / (l_[1] * c10 + l1b * c11);
            const int rowA = qb * 64 + wg * 16 + g;
            float* ob = out + (size_t)b * SS * HH;
            #pragma unroll
            for (int j = 0; j < 8; ++j) {
                const int col = j * 8 + t2;
                float2 v0, v1;
                v0.x = (O[j][0] * c00 + slot[j * 4 + 0] * c01) * iA;
                v0.y = (O[j][1] * c00 + slot[j * 4 + 1] * c01) * iA;
                v1.x = (O[j][2] * c10 + slot[j * 4 + 2] * c11) * iB;
                v1.y = (O[j][3] * c10 + slot[j * 4 + 3] * c11) * iB;
                *(float2*)&ob[(size_t)rowA * HH + col] = v0;
                *(float2*)&ob[(size_t)(rowA + 8) * HH + col] = v1;
            }
        }
        __syncthreads();         // before next pass overwrites Q smem / stages
    }
}

// ---------------------------------------------------------------------------
extern "C" void kernel_launch(void* const* d_in, const int* in_sizes, int n_in,
                              void* d_out, int out_size)
{
    (void)in_sizes; (void)n_in; (void)out_size;
    const float* x  = (const float*)d_in[0];
    const float* Wq = (const float*)d_in[1];
    const float* Wk = (const float*)d_in[2];
    const float* Wv = (const float*)d_in[3];
    float* out = (float*)d_out;

    static int attr_set = 0;
    const int gemm_smem = 2 * G_STG;                // 147456
    const int attn_smem = A_SMEM;                   // 119808
    if (!attr_set) {
        cudaFuncSetAttribute(qkv_mma_kernel,
                             cudaFuncAttributeMaxDynamicSharedMemorySize, gemm_smem);
        cudaFuncSetAttribute(attn_mma_kernel,
                             cudaFuncAttributeMaxDynamicSharedMemorySize, attn_smem);
        attr_set = 1;
    }

    wconv_kernel<<<(NTOT * DD + 255) / 256, 256>>>(Wq, Wk, Wv);
    qkv_mma_kernel<<<SS * BB / 64, 256, gemm_smem>>>(x);
    attn_mma_kernel<<<dim3(32, 4), 256, attn_smem>>>(out);
}

// round 12
// speedup vs baseline: 4.0962x; 1.0588x over previous
#include <cuda_runtime.h>
#include <cuda_bf16.h>
#include <cuda_fp16.h>
#include <cstdint>

#define BB 4
#define SS 4096
#define DD 1024
#define HH 64
#define NTOT 192

// Attention operands: Q single fp16 (carries 0.125*log2e), K fp16 hi/lo, V fp16.
__device__ __half g_Q16[BB * SS * HH];
__device__ __half g_K16h[BB * SS * HH];
__device__ __half g_K16l[BB * SS * HH];
__device__ __half g_V16[BB * SS * HH];
// W hi/lo bf16, transposed to [N=192][K=1024]; Wq pre-scaled by 0.125*log2(e)
__device__ __nv_bfloat16 g_wh[NTOT * DD];
__device__ __nv_bfloat16 g_wl[NTOT * DD];

// ---------------------------------------------------------------------------
// Stable-PTX helpers (harness emits compute_103 PTX: no tcgen05 allowed)
// ---------------------------------------------------------------------------
__device__ __forceinline__ uint32_t smem_u32(const void* p) {
    uint32_t a;
    asm("{ .reg .u64 t; cvta.to.shared.u64 t, %1; cvt.u32.u64 %0, t; }" : "=r"(a) : "l"(p));
    return a;
}
__device__ __forceinline__ void mma_bf16(float* c, const uint32_t* a, const uint32_t* b) {
    asm volatile(
        "mma.sync.aligned.m16n8k16.row.col.f32.bf16.bf16.f32 "
        "{%0,%1,%2,%3}, {%4,%5,%6,%7}, {%8,%9}, {%0,%1,%2,%3};"
        : "+f"(c[0]), "+f"(c[1]), "+f"(c[2]), "+f"(c[3])
        : "r"(a[0]), "r"(a[1]), "r"(a[2]), "r"(a[3]), "r"(b[0]), "r"(b[1]));
}
__device__ __forceinline__ void mma_f16(float* c, const uint32_t* a, const uint32_t* b) {
    asm volatile(
        "mma.sync.aligned.m16n8k16.row.col.f32.f16.f16.f32 "
        "{%0,%1,%2,%3}, {%4,%5,%6,%7}, {%8,%9}, {%0,%1,%2,%3};"
        : "+f"(c[0]), "+f"(c[1]), "+f"(c[2]), "+f"(c[3])
        : "r"(a[0]), "r"(a[1]), "r"(a[2]), "r"(a[3]), "r"(b[0]), "r"(b[1]));
}
__device__ __forceinline__ void ldsm_x4(uint32_t* r, uint32_t addr) {
    asm volatile("ldmatrix.sync.aligned.m8n8.x4.shared.b16 {%0,%1,%2,%3}, [%4];"
                 : "=r"(r[0]), "=r"(r[1]), "=r"(r[2]), "=r"(r[3]) : "r"(addr));
}
__device__ __forceinline__ void ldsm_x4_t(uint32_t* r, uint32_t addr) {
    asm volatile("ldmatrix.sync.aligned.m8n8.x4.trans.shared.b16 {%0,%1,%2,%3}, [%4];"
                 : "=r"(r[0]), "=r"(r[1]), "=r"(r[2]), "=r"(r[3]) : "r"(addr));
}
__device__ __forceinline__ uint32_t pack_bf16(float lo, float hi) {
    uint32_t r;
    asm("cvt.rn.bf16x2.f32 %0, %1, %2;" : "=r"(r) : "f"(hi), "f"(lo));
    return r;
}
__device__ __forceinline__ uint32_t pack_h2(float lo, float hi) {   // lo -> low half
    uint32_t r;
    asm("cvt.rn.f16x2.f32 %0, %1, %2;" : "=r"(r) : "f"(hi), "f"(lo));
    return r;
}
__device__ __forceinline__ uint32_t ex2_h2(uint32_t h2) {
    uint32_t r;
    asm("ex2.approx.f16x2 %0, %1;" : "=r"(r) : "r"(h2));
    return r;
}
__device__ __forceinline__ float ex2f(float x) {
    float r;
    asm("ex2.approx.f32 %0, %1;" : "=f"(r) : "f"(x));
    return r;
}
// v = hi + lo bf16 split of a float pair (x -> low half, y -> high half)
__device__ __forceinline__ void split2(float x, float y, uint32_t& hi, uint32_t& lo) {
    hi = pack_bf16(x, y);
    float hx = __uint_as_float(hi << 16);
    float hy = __uint_as_float(hi & 0xffff0000u);
    lo = pack_bf16(x - hx, y - hy);
}
// v = hi + lo fp16 split of a float pair
__device__ __forceinline__ void split2h(float x, float y, uint32_t& hi, uint32_t& lo) {
    hi = pack_h2(x, y);
    float2 f = __half22float2(*(__half2*)&hi);
    lo = pack_h2(x - f.x, y - f.y);
}
#define CP_ASYNC16(dst, src) \
    asm volatile("cp.async.cg.shared.global [%0], [%1], 16;" :: "r"(dst), "l"(src) : "memory")
#define CP_COMMIT() asm volatile("cp.async.commit_group;" ::: "memory")
#define CP_WAIT0()  asm volatile("cp.async.wait_group 0;" ::: "memory")
#define GBAR(id)    asm volatile("bar.sync %0, 128;" :: "r"(id) : "memory")

// ---------------------------------------------------------------------------
// wconv: W fp32 [1024,64] x3 -> hi/lo bf16 [192,1024].
// Wq scaled by 0.125*log2(e) so attention scores are in log2 domain (exp2 softmax).
// ---------------------------------------------------------------------------
__global__ void wconv_kernel(const float* __restrict__ Wq,
                             const float* __restrict__ Wk,
                             const float* __restrict__ Wv)
{
    int i = blockIdx.x * 256 + threadIdx.x;
    if (i >= NTOT * DD) return;
    int n = i / DD, k = i - n * DD;
    int t = n >> 6, h = n & 63;
    const float* W = (t == 0) ? Wq : ((t == 1) ? Wk : Wv);
    float v = W[(size_t)k * HH + h] * ((t == 0) ? 0.125f * 1.4426950408889634f : 1.0f);
    __nv_bfloat16 hi = __float2bfloat16(v);
    g_wh[i] = hi;
    g_wl[i] = __float2bfloat16(v - __bfloat162float(hi));
}

// ---------------------------------------------------------------------------
// QKV GEMM: C[16384,192] = x * W^T via split-bf16 HMMA (3 terms).
// KC=32 double-buffered: stage 40KB -> 2 CTAs resident/SM (4 warps/SMSP).
// Row stride 80B (16B-aligned, conflict-free ldmatrix).
// Epilogue: Q -> fp16 single; K -> fp16 hi/lo; V -> fp16.
// ---------------------------------------------------------------------------
#define G_STG   40960
#define G_AH    0
#define G_AL    5120
#define G_BH    10240
#define G_BL    25600

__global__ __launch_bounds__(256, 2) void qkv_mma_kernel(const float* __restrict__ x)
{
    extern __shared__ char smem[];
    const uint32_t sm0 = smem_u32(smem);
    const int tid = threadIdx.x;
    const int wid = tid >> 5, lane = tid & 31;
    const int wm = wid & 1, wn = wid >> 1;
    const int m0 = blockIdx.x * 64;

    const int li  = lane & 7;
    const int r16 = lane & 15;
    const int hfA = (lane >> 4) * 16;
    const int nh8 = ((lane >> 4) & 1) * 8;
    const int kh16 = ((lane >> 3) & 1) * 16;

    float acc[2][6][4];
    #pragma unroll
    for (int mi = 0; mi < 2; ++mi)
        #pragma unroll
        for (int j = 0; j < 6; ++j)
            #pragma unroll
            for (int q = 0; q < 4; ++q) acc[mi][j][q] = 0.0f;

    const int ar   = tid >> 2;          // A row 0..63
    const int ac0e = (tid & 3) * 8;     // A element offset 0,8,16,24

    float4 av[2];
    // ---- prologue: chunk 0 ----
    {
        const float* ap = x + (size_t)(m0 + ar) * DD + ac0e;
        av[0] = *(const float4*)ap;
        av[1] = *(const float4*)(ap + 4);
        #pragma unroll
        for (int i = 0; i < 3; ++i) {                  // 768 x 16B per array
            int id = tid + 256 * i, row = id >> 2, ch = id & 3;
            CP_ASYNC16(sm0 + G_BH + row * 80 + ch * 16, g_wh + (size_t)row * DD + ch * 8);
            CP_ASYNC16(sm0 + G_BL + row * 80 + ch * 16, g_wl + (size_t)row * DD + ch * 8);
        }
        CP_COMMIT();
        uint32_t h0, l0, h1, l1;
        split2(av[0].x, av[0].y, h0, l0);
        split2(av[0].z, av[0].w, h1, l1);
        uint32_t h2, l2, h3, l3;
        split2(av[1].x, av[1].y, h2, l2);
        split2(av[1].z, av[1].w, h3, l3);
        uint4 hv = {h0, h1, h2, h3}, lv = {l0, l1, l2, l3};
        *(uint4*)(smem + G_AH + ar * 80 + ac0e * 2) = hv;
        *(uint4*)(smem + G_AL + ar * 80 + ac0e * 2) = lv;
        CP_WAIT0();
        __syncthreads();
    }

    for (int c = 0; c < 32; ++c) {
        const int s = c & 1;
        const uint32_t sb = sm0 + s * G_STG;

        if (c < 31) {   // prefetch chunk c+1 into the other stage
            const float* ap = x + (size_t)(m0 + ar) * DD + (c + 1) * 32 + ac0e;
            av[0] = *(const float4*)ap;
            av[1] = *(const float4*)(ap + 4);
            const uint32_t ob = sm0 + (s ^ 1) * G_STG;
            #pragma unroll
            for (int i = 0; i < 3; ++i) {
                int id = tid + 256 * i, row = id >> 2, ch = id & 3;
                CP_ASYNC16(ob + G_BH + row * 80 + ch * 16,
                           g_wh + (size_t)row * DD + (c + 1) * 32 + ch * 8);
                CP_ASYNC16(ob + G_BL + row * 80 + ch * 16,
                           g_wl + (size_t)row * DD + (c + 1) * 32 + ch * 8);
            }
            CP_COMMIT();
        }

        // ---- consume stage s: 2 k16-steps ----
        #pragma unroll
        for (int kk = 0; kk < 2; ++kk) {
            uint32_t Ah[2][4], Al[2][4];
            #pragma unroll
            for (int mi = 0; mi < 2; ++mi) {
                uint32_t a = sb + (wm * 32 + mi * 16 + r16) * 80 + kk * 32 + hfA;
                ldsm_x4(Ah[mi], a + G_AH);
                ldsm_x4(Al[mi], a + G_AL);
            }
            uint32_t Bh[6][2], Bl[6][2];
            #pragma unroll
            for (int j2 = 0; j2 < 3; ++j2) {
                uint32_t a = sb + (wn * 48 + j2 * 16 + li + nh8) * 80 + kk * 32 + kh16;
                ldsm_x4(&Bh[2 * j2][0], a + G_BH);
                ldsm_x4(&Bl[2 * j2][0], a + G_BL);
            }
            #pragma unroll
            for (int mi = 0; mi < 2; ++mi)
                #pragma unroll
                for (int j = 0; j < 6; ++j) {
                    mma_bf16(acc[mi][j], Ah[mi], Bh[j]);
                    mma_bf16(acc[mi][j], Ah[mi], Bl[j]);
                    mma_bf16(acc[mi][j], Al[mi], Bh[j]);
                }
        }

        if (c < 31) {   // store converted A into the other stage
            char* st = smem + (s ^ 1) * G_STG;
            uint32_t h0, l0, h1, l1;
            split2(av[0].x, av[0].y, h0, l0);
            split2(av[0].z, av[0].w, h1, l1);
            uint32_t h2, l2, h3, l3;
            split2(av[1].x, av[1].y, h2, l2);
            split2(av[1].z, av[1].w, h3, l3);
            uint4 hv = {h0, h1, h2, h3}, lv = {l0, l1, l2, l3};
            *(uint4*)(st + G_AH + ar * 80 + ac0e * 2) = hv;
            *(uint4*)(st + G_AL + ar * 80 + ac0e * 2) = lv;
        }
        CP_WAIT0();
        __syncthreads();
    }

    // ---- epilogue: Q -> fp16; K -> fp16 hi/lo; V -> fp16 ----
    const int g = lane >> 2, t2 = (lane & 3) * 2;
    #pragma unroll
    for (int mi = 0; mi < 2; ++mi) {
        #pragma unroll
        for (int j = 0; j < 6; ++j) {
            const int nG = wn * 48 + j * 8 + t2;
            const int tns = nG >> 6, h = nG & 63;
            const int rowA = m0 + wm * 32 + mi * 16 + g;
            if (tns == 0) {
                *(uint32_t*)&g_Q16[(size_t)rowA * HH + h] =
                    pack_h2(acc[mi][j][0], acc[mi][j][1]);
                *(uint32_t*)&g_Q16[(size_t)(rowA + 8) * HH + h] =
                    pack_h2(acc[mi][j][2], acc[mi][j][3]);
            } else if (tns == 2) {
                *(uint32_t*)&g_V16[(size_t)rowA * HH + h] =
                    pack_h2(acc[mi][j][0], acc[mi][j][1]);
                *(uint32_t*)&g_V16[(size_t)(rowA + 8) * HH + h] =
                    pack_h2(acc[mi][j][2], acc[mi][j][3]);
            } else {
                uint32_t hi, lo;
                split2h(acc[mi][j][0], acc[mi][j][1], hi, lo);
                *(uint32_t*)&g_K16h[(size_t)rowA * HH + h] = hi;
                *(uint32_t*)&g_K16l[(size_t)rowA * HH + h] = lo;
                split2h(acc[mi][j][2], acc[mi][j][3], hi, lo);
                *(uint32_t*)&g_K16h[(size_t)(rowA + 8) * HH + h] = hi;
                *(uint32_t*)&g_K16l[(size_t)(rowA + 8) * HH + h] = lo;
            }
        }
    }
}

// ---------------------------------------------------------------------------
// Attention (unchanged): causal flash, split-KV across two 4-warp groups.
// QK = 2-term fp16 (q16 x (Kh+Kl)); softmax via ex2.f16x2; PV = 1-term fp16.
// grid (32,4): CTA handles q-blocks {p, 63-p}; group g does kb ≡ g (mod 2).
// ---------------------------------------------------------------------------
#define A_Q   0
#define A_ST0 9216       // 4 stages (2 per group); per stage: Kh | Kl | V (fp16)
#define A_STG 27648
#define A_KH 0
#define A_KL 9216
#define A_V  18432
#define A_SMEM (A_ST0 + 4 * A_STG)    // 119808

__global__ __launch_bounds__(256, 1) void attn_mma_kernel(float* __restrict__ out)
{
    extern __shared__ char smem[];
    const uint32_t sm0 = smem_u32(smem);
    const int b = blockIdx.y, pid = blockIdx.x;
    const int tid = threadIdx.x;
    const int w = tid >> 5, lane = tid & 31;
    const int grp = w >> 2, wg = w & 3;      // group 0/1, warp-in-group 0..3
    const int gtid = tid & 127;              // thread id within group

    const int li   = lane & 7;
    const int r16  = lane & 15;
    const int hfA  = (lane >> 4) * 16;
    const int nh8  = ((lane >> 4) & 1) * 8;
    const int kh16 = ((lane >> 3) & 1) * 16;
    const int sh8  = ((lane >> 3) & 1) * 8;
    const int hh16 = ((lane >> 4) & 1) * 16;
    const int g = lane >> 2, t2 = (lane & 3) * 2;

    const size_t base = (size_t)b * SS * HH;

    for (int pass = 0; pass < 2; ++pass) {
        const int qb = pass ? (63 - pid) : pid;
        const int ng = (qb >= grp) ? (((qb - grp) >> 1) + 1) : 0;

        // prefetch this group's first tile (kb = grp) into its stage 0
        if (ng > 0) {
            const uint32_t ob = sm0 + A_ST0 + (2 * grp) * A_STG;
            const size_t kvo = base + (size_t)grp * 64 * HH;
            #pragma unroll
            for (int i = 0; i < 12; ++i) {
                int id = gtid + 128 * i;
                int arr = id >> 9, rem = id & 511, row = rem >> 3, ch = rem & 7;
                const __half* src = (arr == 0) ? g_K16h : (arr == 1) ? g_K16l : g_V16;
                CP_ASYNC16(ob + arr * 9216 + row * 144 + ch * 16,
                           src + kvo + (size_t)row * HH + ch * 8);
            }
        }
        CP_COMMIT();
        // load Q tile fp16 (all 256 threads; 512 chunks)
        {
            const size_t qo = base + (size_t)qb * 64 * HH;
            #pragma unroll
            for (int i = 0; i < 2; ++i) {
                int id = tid + 256 * i;
                int row = id >> 3, ch = id & 7;
                *(uint4*)(smem + A_Q + row * 144 + ch * 16) =
                    *(const uint4*)(g_Q16 + qo + (size_t)row * HH + ch * 8);
            }
        }
        CP_WAIT0();
        __syncthreads();

        uint32_t q16[4][4];
        #pragma unroll
        for (int kk = 0; kk < 4; ++kk) {
            uint32_t a = sm0 + A_Q + (wg * 16 + r16) * 144 + kk * 32 + hfA;
            ldsm_x4(q16[kk], a);
        }

        float O[8][4];
        float m_[2] = {-1e30f, -1e30f}, l_[2] = {0.0f, 0.0f};
        #pragma unroll
        for (int j = 0; j < 8; ++j)
            #pragma unroll
            for (int q = 0; q < 4; ++q) O[j][q] = 0.0f;

        for (int t = 0; t < ng; ++t) {
            const int kb = grp + 2 * t;
            const int s = t & 1;
            const uint32_t sb = sm0 + A_ST0 + (2 * grp + s) * A_STG;

            if (t + 1 < ng) {     // prefetch this group's next tile (kb+2)
                const uint32_t ob = sm0 + A_ST0 + (2 * grp + (s ^ 1)) * A_STG;
                const size_t kvo = base + (size_t)(kb + 2) * 64 * HH;
                #pragma unroll
                for (int i = 0; i < 12; ++i) {
                    int id = gtid + 128 * i;
                    int arr = id >> 9, rem = id & 511, row = rem >> 3, ch = rem & 7;
                    const __half* src = (arr == 0) ? g_K16h : (arr == 1) ? g_K16l : g_V16;
                    CP_ASYNC16(ob + arr * 9216 + row * 144 + ch * 16,
                               src + kvo + (size_t)row * HH + ch * 8);
                }
                CP_COMMIT();
            }

            // ---- S = q16 (Kh + Kl)^T, 2 terms (log2-domain) ----
            float S[8][4];
            #pragma unroll
            for (int j = 0; j < 8; ++j)
                #pragma unroll
                for (int q = 0; q < 4; ++q) S[j][q] = 0.0f;

            #pragma unroll
            for (int kk = 0; kk < 4; ++kk) {
                uint32_t Kh[8][2], Kl[8][2];
                #pragma unroll
                for (int n2 = 0; n2 < 4; ++n2) {
                    uint32_t a = sb + (n2 * 16 + li + nh8) * 144 + kk * 32 + kh16;
                    ldsm_x4(&Kh[2 * n2][0], a + A_KH);
                    ldsm_x4(&Kl[2 * n2][0], a + A_KL);
                }
                #pragma unroll
                for (int j = 0; j < 8; ++j) {
                    mma_f16(S[j], q16[kk], Kh[j]);
                    mma_f16(S[j], q16[kk], Kl[j]);
                }
            }

            if (kb == qb) {       // diagonal tile: causal mask (local coords)
                const int rA = wg * 16 + g, rB = rA + 8;
                #pragma unroll
                for (int j = 0; j < 8; ++j) {
                    const int c0 = j * 8 + t2;
                    if (c0 > rA)     S[j][0] = -1e30f;
                    if (c0 + 1 > rA) S[j][1] = -1e30f;
                    if (c0 > rB)     S[j][2] = -1e30f;
                    if (c0 + 1 > rB) S[j][3] = -1e30f;
                }
            }

            // ---- online softmax, exp2 domain; P emitted as fp16x2 frags ----
            float mx0 = fmaxf(S[0][0], S[0][1]);
            float mx1 = fmaxf(S[0][2], S[0][3]);
            #pragma unroll
            for (int j = 1; j < 8; ++j) {
                mx0 = fmaxf(mx0, fmaxf(S[j][0], S[j][1]));
                mx1 = fmaxf(mx1, fmaxf(S[j][2], S[j][3]));
            }
            mx0 = fmaxf(mx0, __shfl_xor_sync(0xffffffffu, mx0, 1));
            mx0 = fmaxf(mx0, __shfl_xor_sync(0xffffffffu, mx0, 2));
            mx1 = fmaxf(mx1, __shfl_xor_sync(0xffffffffu, mx1, 1));
            mx1 = fmaxf(mx1, __shfl_xor_sync(0xffffffffu, mx1, 2));
            const float mn0 = fmaxf(m_[0], mx0);
            const float mn1 = fmaxf(m_[1], mx1);
            const float corr0 = ex2f(m_[0] - mn0);
            const float corr1 = ex2f(m_[1] - mn1);
            m_[0] = mn0; m_[1] = mn1;

            uint32_t EA[8], EB[8];
            float rs0 = 0.0f, rs1 = 0.0f;
            #pragma unroll
            for (int j = 0; j < 8; ++j) {
                EA[j] = ex2_h2(pack_h2(S[j][0] - mn0, S[j][1] - mn0));
                EB[j] = ex2_h2(pack_h2(S[j][2] - mn1, S[j][3] - mn1));
                float2 fa = __half22float2(*(__half2*)&EA[j]);
                float2 fb = __half22float2(*(__half2*)&EB[j]);
                rs0 += fa.x + fa.y;
                rs1 += fb.x + fb.y;
            }
            rs0 += __shfl_xor_sync(0xffffffffu, rs0, 1);
            rs0 += __shfl_xor_sync(0xffffffffu, rs0, 2);
            rs1 += __shfl_xor_sync(0xffffffffu, rs1, 1);
            rs1 += __shfl_xor_sync(0xffffffffu, rs1, 2);
            l_[0] = l_[0] * corr0 + rs0;
            l_[1] = l_[1] * corr1 + rs1;
            #pragma unroll
            for (int j = 0; j < 8; ++j) {
                O[j][0] *= corr0; O[j][1] *= corr0;
                O[j][2] *= corr1; O[j][3] *= corr1;
            }

            // ---- O += P V, single-term fp16 ----
            #pragma unroll
            for (int kk = 0; kk < 4; ++kk) {
                uint32_t p[4] = {EA[2 * kk], EB[2 * kk], EA[2 * kk + 1], EB[2 * kk + 1]};
                uint32_t Vf[8][2];
                #pragma unroll
                for (int h2 = 0; h2 < 4; ++h2) {
                    uint32_t a = sb + A_V + (kk * 16 + li + sh8) * 144 + h2 * 32 + hh16;
                    ldsm_x4_t(&Vf[2 * h2][0], a);
                }
                #pragma unroll
                for (int j = 0; j < 8; ++j)
                    mma_f16(O[j], p, Vf[j]);
            }

            CP_WAIT0();
            GBAR(1 + grp);       // group-local barrier (stages are per-group)
        }

        // ---- merge partials: group1 -> smem, group0 combines + writes ----
        __syncthreads();         // all tiles done; stage smem reusable
        float* mb = (float*)(smem + A_ST0);
        if (grp == 1) {
            float* slot = mb + gtid * 36;
            #pragma unroll
            for (int j = 0; j < 8; ++j)
                #pragma unroll
                for (int q = 0; q < 4; ++q) slot[j * 4 + q] = O[j][q];
            slot[32] = m_[0]; slot[33] = m_[1];
            slot[34] = l_[0]; slot[35] = l_[1];
        }
        __syncthreads();
        if (grp == 0) {
            const float* slot = mb + gtid * 36;
            const float m1a = slot[32], m1b = slot[33];
            const float l1a = slot[34], l1b = slot[35];
            const float mnA = fmaxf(m_[0], m1a), mnB = fmaxf(m_[1], m1b);
            const float c00 = ex2f(m_[0] - mnA), c01 = ex2f(m1a - mnA);
            const float c10 = ex2f(m_[1] - mnB), c11 = ex2f(m1b - mnB);
            const float iA = 1.0f / (l_[0] * c00 + l1a * c01);
            const float iB = 1.0f / (l_[1] * c10 + l1b * c11);
            const int rowA = qb * 64 + wg * 16 + g;
            float* ob = out + (size_t)b * SS * HH;
            #pragma unroll
            for (int j = 0; j < 8; ++j) {
                const int col = j * 8 + t2;
                float2 v0, v1;
                v0.x = (O[j][0] * c00 + slot[j * 4 + 0] * c01) * iA;
                v0.y = (O[j][1] * c00 + slot[j * 4 + 1] * c01) * iA;
                v1.x = (O[j][2] * c10 + slot[j * 4 + 2] * c11) * iB;
                v1.y = (O[j][3] * c10 + slot[j * 4 + 3] * c11) * iB;
                *(float2*)&ob[(size_t)rowA * HH + col] = v0;
                *(float2*)&ob[(size_t)(rowA + 8) * HH + col] = v1;
            }
        }
        __syncthreads();         // before next pass overwrites Q smem / stages
    }
}

// ---------------------------------------------------------------------------
extern "C" void kernel_launch(void* const* d_in, const int* in_sizes, int n_in,
                              void* d_out, int out_size)
{
    (void)in_sizes; (void)n_in; (void)out_size;
    const float* x  = (const float*)d_in[0];
    const float* Wq = (const float*)d_in[1];
    const float* Wk = (const float*)d_in[2];
    const float* Wv = (const float*)d_in[3];
    float* out = (float*)d_out;

    static int attr_set = 0;
    const int gemm_smem = 2 * G_STG;                // 81920 -> 2 CTAs/SM
    const int attn_smem = A_SMEM;                   // 119808
    if (!attr_set) {
        cudaFuncSetAttribute(qkv_mma_kernel,
                             cudaFuncAttributeMaxDynamicSharedMemorySize, gemm_smem);
        cudaFuncSetAttribute(attn_mma_kernel,
                             cudaFuncAttributeMaxDynamicSharedMemorySize, attn_smem);
        attr_set = 1;
    }

    wconv_kernel<<<(NTOT * DD + 255) / 256, 256>>>(Wq, Wk, Wv);
    qkv_mma_kernel<<<SS * BB / 64, 256, gemm_smem>>>(x);
    attn_mma_kernel<<<dim3(32, 4), 256, attn_smem>>>(out);
}